// round 10
// baseline (speedup 1.0000x reference)
#include <cuda_runtime.h>
#include <math.h>
#include <stdint.h>

// Problem dims
#define LL  4
#define BB  2
#define SSq 512
#define MMm 512
#define DDd 1024
#define HHh 16
#define DKk 64
#define FFf 4096
#define TTt (SSq + MMm)   // 1024

// ---------------- scratch ----------------
__device__ float g_pos[TTt * DDd];        // tf32 bits
__device__ float g_q  [BB * SSq * DDd];   // fp32 (biases added in fused_attn)
__device__ float g_k  [BB * TTt * DDd];   // tf32 bits
__device__ float g_v  [BB * TTt * DDd];   // tf32 bits
__device__ float g_r  [TTt * DDd];        // tf32 bits
__device__ float g_attn[BB * SSq * DDd];  // tf32 bits
__device__ float g_tmp [BB * SSq * DDd];
__device__ float g_tmp2[BB * SSq * DDd];
__device__ float g_ff  [BB * SSq * FFf];  // tf32 bits
__device__ float g_h   [BB * SSq * DDd];  // fp32 residual
__device__ float g_hc  [BB * SSq * DDd];  // tf32 copy
__device__ float g_h1  [BB * SSq * DDd];  // fp32 residual
__device__ float g_h1c [BB * SSq * DDd];  // tf32 copy
// pre-converted operands (tf32 bits)
__device__ float g_wqc[LL * DDd * DDd];
__device__ float g_wkc[LL * DDd * DDd];
__device__ float g_wvc[LL * DDd * DDd];
__device__ float g_wrc[LL * DDd * DDd];
__device__ float g_woc[LL * DDd * DDd];
__device__ float g_w1c[LL * DDd * FFf];
__device__ float g_w2c[LL * FFf * DDd];
__device__ float g_memc[LL * BB * MMm * DDd];
__device__ float g_xc  [BB * SSq * DDd];

// ---------------- PTX helpers ----------------
__device__ __forceinline__ uint32_t f2tf32(float f) {
    uint32_t u;
    asm("cvt.rna.tf32.f32 %0, %1;" : "=r"(u) : "f"(f));
    return u;
}
__device__ __forceinline__ void mma_tf32(float c[4], const uint32_t a[4], const uint32_t b[2]) {
    asm volatile(
        "mma.sync.aligned.m16n8k8.row.col.f32.tf32.tf32.f32 "
        "{%0,%1,%2,%3},{%4,%5,%6,%7},{%8,%9},{%0,%1,%2,%3};"
        : "+f"(c[0]), "+f"(c[1]), "+f"(c[2]), "+f"(c[3])
        : "r"(a[0]), "r"(a[1]), "r"(a[2]), "r"(a[3]), "r"(b[0]), "r"(b[1]));
}
__device__ __forceinline__ void cp_async16(void* smem, const void* g) {
    uint32_t s = (uint32_t)__cvta_generic_to_shared(smem);
    asm volatile("cp.async.cg.shared.global [%0], [%1], 16;" :: "r"(s), "l"(g));
}
#define CP_COMMIT() asm volatile("cp.async.commit_group;")
#define CP_WAIT(n)  asm volatile("cp.async.wait_group %0;" :: "n"(n))

__device__ __forceinline__ uint32_t sm_u32(const void* p) {
    return (uint32_t)__cvta_generic_to_shared(p);
}
__device__ __forceinline__ void ldsm_x4(uint32_t r[4], uint32_t addr) {
    asm volatile("ldmatrix.sync.aligned.m8n8.x4.shared.b16 {%0,%1,%2,%3}, [%4];"
                 : "=r"(r[0]), "=r"(r[1]), "=r"(r[2]), "=r"(r[3]) : "r"(addr));
}
__device__ __forceinline__ void ldsm_x2(uint32_t r[2], uint32_t addr) {
    asm volatile("ldmatrix.sync.aligned.m8n8.x2.shared.b16 {%0,%1}, [%2];"
                 : "=r"(r[0]), "=r"(r[1]) : "r"(addr));
}

// ---------------- merged bulk fp32 -> tf32-bit convert (9 regions) ----------------
__global__ void cvt_all_kernel(
    const float* __restrict__ i0, float* __restrict__ o0, int n0,
    const float* __restrict__ i1, float* __restrict__ o1, int n1,
    const float* __restrict__ i2, float* __restrict__ o2, int n2,
    const float* __restrict__ i3, float* __restrict__ o3, int n3,
    const float* __restrict__ i4, float* __restrict__ o4, int n4_,
    const float* __restrict__ i5, float* __restrict__ o5, int n5,
    const float* __restrict__ i6, float* __restrict__ o6, int n6,
    const float* __restrict__ i7, float* __restrict__ o7, int n7,
    const float* __restrict__ i8, float* __restrict__ o8, int n8)
{
    const float* in; float* out; int n4;
    switch (blockIdx.y) {
        case 0: in = i0; out = o0; n4 = n0; break;
        case 1: in = i1; out = o1; n4 = n1; break;
        case 2: in = i2; out = o2; n4 = n2; break;
        case 3: in = i3; out = o3; n4 = n3; break;
        case 4: in = i4; out = o4; n4 = n4_; break;
        case 5: in = i5; out = o5; n4 = n5; break;
        case 6: in = i6; out = o6; n4 = n6; break;
        case 7: in = i7; out = o7; n4 = n7; break;
        default: in = i8; out = o8; n4 = n8; break;
    }
    int i = blockIdx.x * 256 + threadIdx.x;
    if (i >= n4) return;
    float4 v = ((const float4*)in)[i];
    uint4 u = make_uint4(f2tf32(v.x), f2tf32(v.y), f2tf32(v.z), f2tf32(v.w));
    ((uint4*)out)[i] = u;
}

// ---------------- positional encodings (tf32 out) ----------------
__global__ void pos_kernel(float* __restrict__ pos)
{
    int idx = blockIdx.x * blockDim.x + threadIdx.x;
    if (idx >= TTt * (DDd / 2)) return;
    int t = idx / (DDd / 2), j = idx % (DDd / 2);
    double invf = exp(((double)(-2 * j) / (double)DDd) * 9.210340371976184);
    double ang  = (double)(TTt - 1 - t) * invf;
    double kk   = floor(ang * 0.15915494309189535);
    float a = (float)(ang - kk * 6.283185307179586);
    pos[(size_t)t * DDd + j]           = __uint_as_float(f2tf32(sinf(a)));
    pos[(size_t)t * DDd + j + DDd / 2] = __uint_as_float(f2tf32(cosf(a)));
}

// ======================================================================
// Async GEMM core (R9 verified): pre-converted tf32 operands, pure
// cp.async -> LDS -> HMMA.
// ======================================================================
template<int BM, int NWN>
__device__ __forceinline__ void gemm_core_async(
    const float* __restrict__ Ag, const float* __restrict__ Bg, float* __restrict__ Cg,
    int N, int K, int lda, float alpha, const float* __restrict__ biasg, int relu,
    int cvt_out)
{
    constexpr int BN = NWN * 32;
    constexpr int NWM = 8 / NWN;
    constexpr int WM = BM / NWM;
    constexpr int MT = WM / 16;
    constexpr int BPITCH = BN + 8;
    constexpr int NA_CH = BM / 64;
    constexpr int NB_CH = BN / 64;

    __shared__ uint32_t As[2][BM][20];
    __shared__ uint32_t Bs[2][16][BPITCH];

    int tid = threadIdx.x, lane = tid & 31, warp = tid >> 5;
    int g = lane >> 2, tg = lane & 3;
    int warp_m = warp % NWM, warp_n = warp / NWM;
    int wm = warp_m * WM, wn = warp_n * 32;

    float acc[MT][4][4];
#pragma unroll
    for (int mt = 0; mt < MT; mt++)
#pragma unroll
        for (int nt = 0; nt < 4; nt++)
#pragma unroll
            for (int i = 0; i < 4; i++) acc[mt][nt][i] = 0.f;

    int ar[NA_CH], ak[NA_CH];
#pragma unroll
    for (int j = 0; j < NA_CH; j++) {
        int c = tid + j * 256;
        ar[j] = c >> 2; ak[j] = (c & 3) * 4;
    }
    int bk[NB_CH], bn[NB_CH];
#pragma unroll
    for (int j = 0; j < NB_CH; j++) {
        int c = tid + j * 256;
        if (BN == 128) { bk[j] = c >> 5; bn[j] = (c & 31) * 4; }
        else           { bk[j] = c >> 4; bn[j] = (c & 15) * 4; }
    }

    int nk = K / 16;

#pragma unroll
    for (int j = 0; j < NA_CH; j++)
        cp_async16(&As[0][ar[j]][ak[j]], Ag + (size_t)ar[j] * lda + ak[j]);
#pragma unroll
    for (int j = 0; j < NB_CH; j++)
        cp_async16(&Bs[0][bk[j]][bn[j]], Bg + (size_t)bk[j] * N + bn[j]);
    CP_COMMIT();

    for (int kt = 0; kt < nk; kt++) {
        int buf = kt & 1;
        bool more = (kt + 1 < nk);
        if (more) {
            int nb = buf ^ 1;
#pragma unroll
            for (int j = 0; j < NA_CH; j++)
                cp_async16(&As[nb][ar[j]][ak[j]],
                           Ag + (size_t)ar[j] * lda + (kt + 1) * 16 + ak[j]);
#pragma unroll
            for (int j = 0; j < NB_CH; j++)
                cp_async16(&Bs[nb][bk[j]][bn[j]],
                           Bg + (size_t)((kt + 1) * 16 + bk[j]) * N + bn[j]);
            CP_COMMIT();
            CP_WAIT(1);
        } else {
            CP_WAIT(0);
        }
        __syncthreads();

#pragma unroll
        for (int ks = 0; ks < 2; ks++) {
            uint32_t af[MT][4], bf[4][2];
#pragma unroll
            for (int mt = 0; mt < MT; mt++) {
                int row = wm + mt * 16;
                af[mt][0] = As[buf][row + g][ks * 8 + tg];
                af[mt][1] = As[buf][row + g + 8][ks * 8 + tg];
                af[mt][2] = As[buf][row + g][ks * 8 + tg + 4];
                af[mt][3] = As[buf][row + g + 8][ks * 8 + tg + 4];
            }
#pragma unroll
            for (int nt = 0; nt < 4; nt++) {
                int col = wn + nt * 8 + g;
                bf[nt][0] = Bs[buf][ks * 8 + tg][col];
                bf[nt][1] = Bs[buf][ks * 8 + tg + 4][col];
            }
#pragma unroll
            for (int mt = 0; mt < MT; mt++)
#pragma unroll
                for (int nt = 0; nt < 4; nt++) mma_tf32(acc[mt][nt], af[mt], bf[nt]);
        }
        if (more) __syncthreads();
    }

#pragma unroll
    for (int mt = 0; mt < MT; mt++) {
#pragma unroll
        for (int nt = 0; nt < 4; nt++) {
            int row = wm + mt * 16 + g;
            int col = wn + nt * 8 + tg * 2;
            float bx0 = 0.f, bx1 = 0.f;
            if (biasg) { bx0 = biasg[col]; bx1 = biasg[col + 1]; }
            float v0 = acc[mt][nt][0] * alpha + bx0;
            float v1 = acc[mt][nt][1] * alpha + bx1;
            float v2 = acc[mt][nt][2] * alpha + bx0;
            float v3 = acc[mt][nt][3] * alpha + bx1;
            if (relu) {
                v0 = fmaxf(v0, 0.f); v1 = fmaxf(v1, 0.f);
                v2 = fmaxf(v2, 0.f); v3 = fmaxf(v3, 0.f);
            }
            if (cvt_out) {
                v0 = __uint_as_float(f2tf32(v0));
                v1 = __uint_as_float(f2tf32(v1));
                v2 = __uint_as_float(f2tf32(v2));
                v3 = __uint_as_float(f2tf32(v3));
            }
            *(float2*)(Cg + (size_t)row * N + col)       = make_float2(v0, v1);
            *(float2*)(Cg + (size_t)(row + 8) * N + col) = make_float2(v2, v3);
        }
    }
}

template<int BM, int NWN>
__global__ void __launch_bounds__(256) tc_gemm_k(
    const float* __restrict__ A, const float* __restrict__ B, float* __restrict__ C,
    int N, int K, float alpha, const float* __restrict__ bias, int relu, int cvt_out)
{
    constexpr int BN = NWN * 32;
    const float* Ag = A + (size_t)blockIdx.y * BM * K;
    const float* Bg = B + (size_t)blockIdx.x * BN;
    float* Cg = C + (size_t)blockIdx.y * BM * N + (size_t)blockIdx.x * BN;
    const float* bg = bias ? bias + (size_t)blockIdx.x * BN : nullptr;
    gemm_core_async<BM, NWN>(Ag, Bg, Cg, N, K, K, alpha, bg, relu, cvt_out);
}

template<int BM, int NWN>
__global__ void __launch_bounds__(256) tc_gemm_splitk(
    const float* __restrict__ A, const float* __restrict__ B,
    float* __restrict__ C0, float* __restrict__ C1,
    int N, int K, const float* __restrict__ bias)
{
    constexpr int BN = NWN * 32;
    int z = blockIdx.z;
    int K2 = K >> 1;
    const float* Ag = A + (size_t)blockIdx.y * BM * K + (size_t)z * K2;
    const float* Bg = B + (size_t)z * K2 * N + (size_t)blockIdx.x * BN;
    float* C = z ? C1 : C0;
    float* Cg = C + (size_t)blockIdx.y * BM * N + (size_t)blockIdx.x * BN;
    const float* bg = (bias && z == 0) ? bias + (size_t)blockIdx.x * BN : nullptr;
    gemm_core_async<BM, NWN>(Ag, Bg, Cg, N, K2, K, 1.f, bg, 0, 0);
}

// grouped q/k/v/r projections (R9 verified)
__global__ void __launch_bounds__(256) grouped_qkvr(
    const float* __restrict__ hcc, const float* __restrict__ memc, const float* __restrict__ pos,
    const float* __restrict__ Wq, const float* __restrict__ Wk,
    const float* __restrict__ Wv, const float* __restrict__ Wr,
    float* __restrict__ q, float* __restrict__ k, float* __restrict__ v, float* __restrict__ r)
{
    int y = blockIdx.y;
    const float* Ag; const float* B; float* C; float alpha = 1.f; int cvt = 1;
    if (y < 8) {
        Ag = hcc + (size_t)y * 128 * DDd; B = Wq; C = q + (size_t)y * 128 * DDd;
        alpha = 0.125f; cvt = 0;
    } else if (y < 40) {
        int yy = (y < 24) ? y - 8 : y - 24;
        int row0 = yy * 128;
        int b = row0 >> 10, t0 = row0 & 1023;
        Ag = (t0 < MMm) ? memc + ((size_t)b * MMm + t0) * DDd
                        : hcc  + ((size_t)b * SSq + (t0 - MMm)) * DDd;
        if (y < 24) { B = Wk; C = k + (size_t)yy * 128 * DDd; }
        else        { B = Wv; C = v + (size_t)yy * 128 * DDd; }
    } else {
        int yy = y - 40;
        Ag = pos + (size_t)yy * 128 * DDd; B = Wr; C = r + (size_t)yy * 128 * DDd;
    }
    const float* Bg = B + (size_t)blockIdx.x * 128;
    float* Cg = C + (size_t)blockIdx.x * 128;
    gemm_core_async<128, 4>(Ag, Bg, Cg, DDd, DDd, DDd, alpha, nullptr, 0, cvt);
}

// ======================================================================
// Flash fused attention: ldmatrix fragment loads (QK A/B, PV A).
// ======================================================================
#define SMT   32
#define TN    64
#define QPITCH 68
#define WPITCH 100
#define SMEM_ATTN_FLOATS (2*SMT*QPITCH + 64*QPITCH + 96*QPITCH + 64*QPITCH + SMT*WPITCH + SMT*QPITCH + 128 + 128 + 32 + 32)
#define SMEM_ATTN_BYTES  (SMEM_ATTN_FLOATS * 4)

__global__ void __launch_bounds__(256) fused_attn(
    const float* __restrict__ q, const float* __restrict__ k, const float* __restrict__ v,
    const float* __restrict__ r, const float* __restrict__ rwb, const float* __restrict__ rrb,
    float* __restrict__ attn)
{
    extern __shared__ float sm[];
    uint32_t* Qcb  = (uint32_t*)sm;
    uint32_t* Qrb  = Qcb + SMT * QPITCH;
    uint32_t* Ktb  = Qrb + SMT * QPITCH;
    uint32_t* Rwb  = Ktb + 64 * QPITCH;
    uint32_t* Vtb  = Rwb + 96 * QPITCH;
    float* QRW     = (float*)(Vtb + 64 * QPITCH);
    uint32_t* Pt   = (uint32_t*)(QRW + SMT * WPITCH);
    float* partm   = (float*)(Pt + SMT * QPITCH);
    float* parts   = partm + 128;
    float* rowm    = parts + 128;
    float* rowsum  = rowm + 32;

    int tid = threadIdx.x, lane = tid & 31, warp = tid >> 5;
    int g = lane >> 2, tg = lane & 3;
    int s0 = (15 - blockIdx.x) * SMT;
    int b = blockIdx.y >> 4, h = blockIdx.y & 15;

    const float* qb = q + (size_t)b * SSq * DDd + h * DKk;
    const float* kb = k + (size_t)b * TTt * DDd + h * DKk;
    const float* vb = v + (size_t)b * TTt * DDd + h * DKk;
    const float* rb = r + h * DKk;
    const float* wbv = rwb + h * DKk;
    const float* rbv = rrb + h * DKk;

    int ntiles = (s0 + 543) / 64 + 1;
    int lrow = tid >> 4, lk0 = (tid & 15) * 4;

    auto issue_KR = [&](int it) {
        if (it < ntiles) {
            int t0 = it * TN, jb = t0 - s0 + 480;
#pragma unroll
            for (int j = 0; j < 4; j++) {
                int row = lrow + j * 16;
                cp_async16(&Ktb[row * QPITCH + lk0], kb + (size_t)(t0 + row) * DDd + lk0);
            }
#pragma unroll
            for (int j = 0; j < 6; j++) {
                int row = lrow + j * 16;
                int jg = jb + row; if (jg > TTt - 1) jg = TTt - 1;
                cp_async16(&Rwb[row * QPITCH + lk0], rb + (size_t)jg * DDd + lk0);
            }
        }
        CP_COMMIT();
    };
    auto issue_V = [&](int it) {
        if (it < ntiles) {
            int t0 = it * TN;
#pragma unroll
            for (int j = 0; j < 4; j++) {
                int row = lrow + j * 16;
                cp_async16(&Vtb[row * QPITCH + lk0], vb + (size_t)(t0 + row) * DDd + lk0);
            }
        }
        CP_COMMIT();
    };

    issue_KR(0);
    issue_V(0);

#pragma unroll
    for (int j = 0; j < 2; j++) {
        int c = tid + j * 256;
        int row = c >> 4, k0 = (c & 15) * 4;
        float4 qv = *(const float4*)(qb + (size_t)(s0 + row) * DDd + k0);
        float4 w4 = *(const float4*)(wbv + k0);
        float4 r4 = *(const float4*)(rbv + k0);
        Qcb[row * QPITCH + k0 + 0] = f2tf32(qv.x + w4.x);
        Qcb[row * QPITCH + k0 + 1] = f2tf32(qv.y + w4.y);
        Qcb[row * QPITCH + k0 + 2] = f2tf32(qv.z + w4.z);
        Qcb[row * QPITCH + k0 + 3] = f2tf32(qv.w + w4.w);
        Qrb[row * QPITCH + k0 + 0] = f2tf32(qv.x + r4.x);
        Qrb[row * QPITCH + k0 + 1] = f2tf32(qv.y + r4.y);
        Qrb[row * QPITCH + k0 + 2] = f2tf32(qv.z + r4.z);
        Qrb[row * QPITCH + k0 + 3] = f2tf32(qv.w + r4.w);
    }
    if (tid < 32) { rowm[tid] = -1e30f; rowsum[tid] = 0.f; }

    int wm2 = (warp & 1) * 16;
    int wn2 = (warp >> 1) * 16;
    int wn3 = (warp >> 1) * 24;
    int wi  = warp >> 1;
    int r1 = wm2 + g, r2 = r1 + 8;

    // ---- ldmatrix lane address patterns (tf32 fragments) ----
    // A-pattern (Qcb/Qrb/Pt, rows base..base+16): reg j <- tile j
    //   lanes 0-7: rows+[0,8) col 0 | 8-15: rows+8 col 0 | 16-23: rows col 4 | 24-31: rows+8 col 4
    int a_row = (lane & 7) + ((lane >> 3) & 1) * 8;
    int a_col = (lane >> 4) * 4;
    // B-pattern (Ktb/Rwb x4, rows base..base+16):
    //   lanes 0-7: rows col 0 | 8-15: rows col 4 | 16-23: rows+8 col 0 | 24-31: rows+8 col 4
    int b_row = (lane & 7) + ((lane >> 4) & 1) * 8;
    int b_col = ((lane >> 3) & 1) * 4;
    // x2-pattern (Rwb third n-tile, rows base..base+8): lanes 0-7 col 0, 8-15 col 4
    int c_row = lane & 7;
    int c_col = ((lane >> 3) & 1) * 4;

    uint32_t qc_a = sm_u32(&Qcb[(wm2 + a_row) * QPITCH + a_col]);
    uint32_t qr_a = sm_u32(&Qrb[(wm2 + a_row) * QPITCH + a_col]);
    uint32_t pt_a = sm_u32(&Pt [(wm2 + a_row) * QPITCH + a_col]);
    uint32_t kt_a = sm_u32(&Ktb[(wn2 + b_row) * QPITCH + b_col]);
    uint32_t rw4_a = sm_u32(&Rwb[(wn3 + b_row) * QPITCH + b_col]);
    uint32_t rw2_a = sm_u32(&Rwb[(wn3 + 16 + c_row) * QPITCH + c_col]);

    float oacc[2][4];
#pragma unroll
    for (int nt = 0; nt < 2; nt++)
#pragma unroll
        for (int i = 0; i < 4; i++) oacc[nt][i] = 0.f;

    for (int it = 0; it < ntiles; it++) {
        int t0 = it * TN;
        CP_WAIT(1);
        __syncthreads();

        float ca[2][4], ra[3][4];
#pragma unroll
        for (int nt = 0; nt < 2; nt++)
#pragma unroll
            for (int i = 0; i < 4; i++) ca[nt][i] = 0.f;
#pragma unroll
        for (int nt = 0; nt < 3; nt++)
#pragma unroll
            for (int i = 0; i < 4; i++) ra[nt][i] = 0.f;

#pragma unroll
        for (int k8 = 0; k8 < 64; k8 += 8) {
            uint32_t koff = k8 * 4;
            uint32_t af[4], afr[4], bk4[4], br4[4], br2[2];
            ldsm_x4(af,  qc_a + koff);
            ldsm_x4(afr, qr_a + koff);
            ldsm_x4(bk4, kt_a + koff);
            ldsm_x4(br4, rw4_a + koff);
            ldsm_x2(br2, rw2_a + koff);
            {
                uint32_t bf0[2] = {bk4[0], bk4[1]};
                uint32_t bf1[2] = {bk4[2], bk4[3]};
                mma_tf32(ca[0], af, bf0);
                mma_tf32(ca[1], af, bf1);
            }
            {
                uint32_t bf0[2] = {br4[0], br4[1]};
                uint32_t bf1[2] = {br4[2], br4[3]};
                mma_tf32(ra[0], afr, bf0);
                mma_tf32(ra[1], afr, bf1);
                mma_tf32(ra[2], afr, br2);
            }
        }
#pragma unroll
        for (int nt = 0; nt < 3; nt++) {
            int c0 = wn3 + nt * 8 + tg * 2;
            QRW[r1 * WPITCH + c0]     = ra[nt][0];
            QRW[r1 * WPITCH + c0 + 1] = ra[nt][1];
            QRW[r2 * WPITCH + c0]     = ra[nt][2];
            QRW[r2 * WPITCH + c0 + 1] = ra[nt][3];
        }
        __syncthreads();

        issue_KR(it + 1);

        float l[2][4];
#pragma unroll
        for (int nt = 0; nt < 2; nt++) {
            int tts = wn2 + nt * 8 + tg * 2;
#pragma unroll
            for (int i = 0; i < 4; i++) {
                int si = wm2 + g + ((i >= 2) ? 8 : 0);
                int tt = tts + (i & 1);
                int t = t0 + tt, s = s0 + si;
                l[nt][i] = (t - s <= MMm)
                    ? ca[nt][i] + QRW[si * WPITCH + tt + (SMT - 1) - si]
                    : -1e30f;
            }
        }
        float mx1 = fmaxf(fmaxf(l[0][0], l[0][1]), fmaxf(l[1][0], l[1][1]));
        float mx2 = fmaxf(fmaxf(l[0][2], l[0][3]), fmaxf(l[1][2], l[1][3]));
        mx1 = fmaxf(mx1, __shfl_xor_sync(0xffffffffu, mx1, 1));
        mx1 = fmaxf(mx1, __shfl_xor_sync(0xffffffffu, mx1, 2));
        mx2 = fmaxf(mx2, __shfl_xor_sync(0xffffffffu, mx2, 1));
        mx2 = fmaxf(mx2, __shfl_xor_sync(0xffffffffu, mx2, 2));
        if (tg == 0) { partm[r1 * 4 + wi] = mx1; partm[r2 * 4 + wi] = mx2; }

        CP_WAIT(1);
        __syncthreads();

        float tm1 = fmaxf(fmaxf(partm[r1 * 4 + 0], partm[r1 * 4 + 1]),
                          fmaxf(partm[r1 * 4 + 2], partm[r1 * 4 + 3]));
        float tm2 = fmaxf(fmaxf(partm[r2 * 4 + 0], partm[r2 * 4 + 1]),
                          fmaxf(partm[r2 * 4 + 2], partm[r2 * 4 + 3]));
        float m1 = fmaxf(rowm[r1], tm1);
        float m2 = fmaxf(rowm[r2], tm2);
        float c1 = __expf(rowm[r1] - m1);
        float c2 = __expf(rowm[r2] - m2);
        float s1a = 0.f, s2a = 0.f;
#pragma unroll
        for (int nt = 0; nt < 2; nt++) {
            int tts = wn2 + nt * 8 + tg * 2;
            float p0 = __expf(l[nt][0] - m1);
            float p1 = __expf(l[nt][1] - m1);
            float p2 = __expf(l[nt][2] - m2);
            float p3 = __expf(l[nt][3] - m2);
            Pt[r1 * QPITCH + tts]     = f2tf32(p0);
            Pt[r1 * QPITCH + tts + 1] = f2tf32(p1);
            Pt[r2 * QPITCH + tts]     = f2tf32(p2);
            Pt[r2 * QPITCH + tts + 1] = f2tf32(p3);
            s1a += p0 + p1;
            s2a += p2 + p3;
        }
        s1a += __shfl_xor_sync(0xffffffffu, s1a, 1);
        s1a += __shfl_xor_sync(0xffffffffu, s1a, 2);
        s2a += __shfl_xor_sync(0xffffffffu, s2a, 1);
        s2a += __shfl_xor_sync(0xffffffffu, s2a, 2);
        if (tg == 0) { parts[r1 * 4 + wi] = s1a; parts[r2 * 4 + wi] = s2a; }
#pragma unroll
        for (int nt = 0; nt < 2; nt++) {
            oacc[nt][0] *= c1; oacc[nt][1] *= c1;
            oacc[nt][2] *= c2; oacc[nt][3] *= c2;
        }
        __syncthreads();

        if (wi == 0 && tg == 0) {
            rowsum[r1] = rowsum[r1] * c1 +
                parts[r1 * 4 + 0] + parts[r1 * 4 + 1] + parts[r1 * 4 + 2] + parts[r1 * 4 + 3];
            rowm[r1] = m1;
            rowsum[r2] = rowsum[r2] * c2 +
                parts[r2 * 4 + 0] + parts[r2 * 4 + 1] + parts[r2 * 4 + 2] + parts[r2 * 4 + 3];
            rowm[r2] = m2;
        }

#pragma unroll
        for (int k8 = 0; k8 < 64; k8 += 8) {
            uint32_t af[4];
            ldsm_x4(af, pt_a + k8 * 4);
#pragma unroll
            for (int nt = 0; nt < 2; nt++) {
                uint32_t bf[2];
                int col = wn2 + nt * 8 + g;
                bf[0] = Vtb[(k8 + tg) * QPITCH + col];
                bf[1] = Vtb[(k8 + tg + 4) * QPITCH + col];
                mma_tf32(oacc[nt], af, bf);
            }
        }
        __syncthreads();
        issue_V(it + 1);
    }

    __syncthreads();
    float inv1 = 1.f / rowsum[r1];
    float inv2 = 1.f / rowsum[r2];
    float* ob = attn + ((size_t)b * SSq + s0) * DDd + h * DKk;
#pragma unroll
    for (int nt = 0; nt < 2; nt++) {
        int c0 = wn2 + nt * 8 + tg * 2;
        *(float2*)(ob + (size_t)r1 * DDd + c0) = make_float2(
            __uint_as_float(f2tf32(oacc[nt][0] * inv1)),
            __uint_as_float(f2tf32(oacc[nt][1] * inv1)));
        *(float2*)(ob + (size_t)r2 * DDd + c0) = make_float2(
            __uint_as_float(f2tf32(oacc[nt][2] * inv2)),
            __uint_as_float(f2tf32(oacc[nt][3] * inv2)));
    }
}

// ---------------- residual + LayerNorm over (x0 + x1 + res), dual output ----------------
__global__ void ln_kernel2(const float* __restrict__ x0, const float* __restrict__ x1,
                           const float* __restrict__ res,
                           const float* __restrict__ g, const float* __restrict__ b,
                           float* __restrict__ out, float* __restrict__ outc)
{
    int row = blockIdx.x;
    const float* xr0 = x0 + (size_t)row * DDd;
    const float* xr1 = x1 + (size_t)row * DDd;
    const float* rr  = res + (size_t)row * DDd;
    __shared__ float redA[33], redB[33];
    int tid = threadIdx.x;

    float loc[4];
    float s1 = 0.f, s2 = 0.f;
#pragma unroll
    for (int i = 0; i < 4; i++) {
        int d = tid + i * 256;
        float v = xr0[d] + xr1[d] + rr[d];
        loc[i] = v;
        s1 += v;
        s2 += v * v;
    }
#pragma unroll
    for (int o = 16; o; o >>= 1) {
        s1 += __shfl_xor_sync(0xffffffffu, s1, o);
        s2 += __shfl_xor_sync(0xffffffffu, s2, o);
    }
    if ((tid & 31) == 0) { redA[tid >> 5] = s1; redB[tid >> 5] = s2; }
    __syncthreads();
    if (tid < 32) {
        float a = (tid < 8) ? redA[tid] : 0.f;
        float c = (tid < 8) ? redB[tid] : 0.f;
#pragma unroll
        for (int o = 4; o; o >>= 1) {
            a += __shfl_xor_sync(0xffffffffu, a, o);
            c += __shfl_xor_sync(0xffffffffu, c, o);
        }
        if (tid == 0) { redA[32] = a; redB[32] = c; }
    }
    __syncthreads();
    float mu  = redA[32] * (1.f / DDd);
    float var = redB[32] * (1.f / DDd) - mu * mu;
    float rstd = rsqrtf(var + 1e-5f);
#pragma unroll
    for (int i = 0; i < 4; i++) {
        int d = tid + i * 256;
        float o = (loc[i] - mu) * rstd * g[d] + b[d];
        out[(size_t)row * DDd + d] = o;
        if (outc) outc[(size_t)row * DDd + d] = __uint_as_float(f2tf32(o));
    }
}

// ---------------- host-side orchestration ----------------
extern "C" void kernel_launch(void* const* d_in, const int* in_sizes, int n_in,
                              void* d_out, int out_size)
{
    const float* x      = (const float*)d_in[0];
    const float* memory = (const float*)d_in[1];
    const float* Wq  = (const float*)d_in[2];
    const float* Wk  = (const float*)d_in[3];
    const float* Wv  = (const float*)d_in[4];
    const float* Wr  = (const float*)d_in[5];
    const float* Wo  = (const float*)d_in[6];
    const float* rwb = (const float*)d_in[7];
    const float* rrb = (const float*)d_in[8];
    const float* ln1g = (const float*)d_in[9];
    const float* ln1b = (const float*)d_in[10];
    const float* ln2g = (const float*)d_in[11];
    const float* ln2b = (const float*)d_in[12];
    const float* W1  = (const float*)d_in[13];
    const float* b1  = (const float*)d_in[14];
    const float* W2  = (const float*)d_in[15];
    const float* b2  = (const float*)d_in[16];
    float* out = (float*)d_out;

    float *pos, *q, *k, *v, *r, *attn, *tmp, *tmp2, *ff, *h, *hc, *h1, *h1c;
    float *wqc, *wkc, *wvc, *wrc, *woc, *w1c, *w2c, *memc, *xc;
    cudaGetSymbolAddress((void**)&pos,  g_pos);
    cudaGetSymbolAddress((void**)&q,    g_q);
    cudaGetSymbolAddress((void**)&k,    g_k);
    cudaGetSymbolAddress((void**)&v,    g_v);
    cudaGetSymbolAddress((void**)&r,    g_r);
    cudaGetSymbolAddress((void**)&attn, g_attn);
    cudaGetSymbolAddress((void**)&tmp,  g_tmp);
    cudaGetSymbolAddress((void**)&tmp2, g_tmp2);
    cudaGetSymbolAddress((void**)&ff,   g_ff);
    cudaGetSymbolAddress((void**)&h,    g_h);
    cudaGetSymbolAddress((void**)&hc,   g_hc);
    cudaGetSymbolAddress((void**)&h1,   g_h1);
    cudaGetSymbolAddress((void**)&h1c,  g_h1c);
    cudaGetSymbolAddress((void**)&wqc,  g_wqc);
    cudaGetSymbolAddress((void**)&wkc,  g_wkc);
    cudaGetSymbolAddress((void**)&wvc,  g_wvc);
    cudaGetSymbolAddress((void**)&wrc,  g_wrc);
    cudaGetSymbolAddress((void**)&woc,  g_woc);
    cudaGetSymbolAddress((void**)&w1c,  g_w1c);
    cudaGetSymbolAddress((void**)&w2c,  g_w2c);
    cudaGetSymbolAddress((void**)&memc, g_memc);
    cudaGetSymbolAddress((void**)&xc,   g_xc);

    cudaFuncSetAttribute(fused_attn, cudaFuncAttributeMaxDynamicSharedMemorySize,
                         SMEM_ATTN_BYTES);

    // one merged convert launch (9 regions; chunk counts in float4s)
    {
        int nw = (LL * DDd * DDd) / 4;            // 1,048,576
        int nf = (LL * DDd * FFf) / 4;            // 4,194,304
        int nm = (LL * BB * MMm * DDd) / 4;       // 1,048,576
        int nx = (BB * SSq * DDd) / 4;            // 262,144
        dim3 gC((nf + 255) / 256, 9);
        cvt_all_kernel<<<gC, 256>>>(
            Wq, wqc, nw, Wk, wkc, nw, Wv, wvc, nw, Wr, wrc, nw, Wo, woc, nw,
            W1, w1c, nf, W2, w2c, nf, memory, memc, nm, x, xc, nx);
    }

    pos_kernel<<<(TTt * (DDd / 2) + 255) / 256, 256>>>(pos);

    const float* hcur  = x;
    const float* hcurc = xc;
    for (int l = 0; l < LL; l++) {
        dim3 gG(DDd / 128, 48);
        grouped_qkvr<<<gG, 256>>>(hcurc, memc + (size_t)l * BB * MMm * DDd, pos,
                                  wqc + (size_t)l * DDd * DDd, wkc + (size_t)l * DDd * DDd,
                                  wvc + (size_t)l * DDd * DDd, wrc + (size_t)l * DDd * DDd,
                                  q, k, v, r);

        dim3 gA(SSq / SMT, BB * HHh);
        fused_attn<<<gA, 256, SMEM_ATTN_BYTES>>>(
            q, k, v, r, rwb + (size_t)l * HHh * DKk, rrb + (size_t)l * HHh * DKk, attn);

        dim3 gO(DDd / 128, (BB * SSq) / 64, 2);
        tc_gemm_splitk<64, 4><<<gO, 256>>>(attn, woc + (size_t)l * DDd * DDd,
                                           tmp, tmp2, DDd, DDd, nullptr);
        ln_kernel2<<<BB * SSq, 256>>>(tmp, tmp2, hcur,
                                      ln1g + l * DDd, ln1b + l * DDd, h1, h1c);

        dim3 gF1(FFf / 128, (BB * SSq) / 128);
        tc_gemm_k<128, 4><<<gF1, 256>>>(h1c, w1c + (size_t)l * DDd * FFf, ff,
                                        FFf, DDd, 1.f, b1 + l * FFf, 1, 1);
        dim3 gF2(DDd / 128, (BB * SSq) / 64, 2);
        tc_gemm_splitk<64, 4><<<gF2, 256>>>(ff, w2c + (size_t)l * FFf * DDd,
                                            tmp, tmp2, DDd, FFf, b2 + l * DDd);

        if (l == LL - 1) {
            ln_kernel2<<<BB * SSq, 256>>>(tmp, tmp2, h1,
                                          ln2g + l * DDd, ln2b + l * DDd, out, nullptr);
        } else {
            ln_kernel2<<<BB * SSq, 256>>>(tmp, tmp2, h1,
                                          ln2g + l * DDd, ln2b + l * DDd, h, hc);
            hcur = h;
            hcurc = hc;
        }
    }
}

// round 11
// speedup vs baseline: 1.0023x; 1.0023x over previous
#include <cuda_runtime.h>
#include <math.h>
#include <stdint.h>

// Problem dims
#define LL  4
#define BB  2
#define SSq 512
#define MMm 512
#define DDd 1024
#define HHh 16
#define DKk 64
#define FFf 4096
#define TTt (SSq + MMm)   // 1024

// ---------------- scratch ----------------
__device__ float g_pos[TTt * DDd];        // tf32 bits
__device__ float g_q  [BB * SSq * DDd];   // fp32 (biases added in fused_attn)
__device__ float g_k  [BB * TTt * DDd];   // tf32 bits
__device__ float g_v  [BB * TTt * DDd];   // tf32 bits
__device__ float g_r  [TTt * DDd];        // tf32 bits
__device__ float g_attn[BB * SSq * DDd];  // tf32 bits
__device__ float g_tmp [BB * SSq * DDd];
__device__ float g_tmp2[BB * SSq * DDd];
__device__ float g_ff  [BB * SSq * FFf];  // tf32 bits
__device__ float g_h   [BB * SSq * DDd];  // fp32 residual
__device__ float g_hc  [BB * SSq * DDd];  // tf32 copy
__device__ float g_h1  [BB * SSq * DDd];  // fp32 residual
__device__ float g_h1c [BB * SSq * DDd];  // tf32 copy
// pre-converted operands (tf32 bits)
__device__ float g_wqc[LL * DDd * DDd];
__device__ float g_wkc[LL * DDd * DDd];
__device__ float g_wvc[LL * DDd * DDd];
__device__ float g_wrc[LL * DDd * DDd];
__device__ float g_woc[LL * DDd * DDd];
__device__ float g_w1c[LL * DDd * FFf];
__device__ float g_w2c[LL * FFf * DDd];
__device__ float g_memc[LL * BB * MMm * DDd];
__device__ float g_xc  [BB * SSq * DDd];

// ---------------- PTX helpers ----------------
__device__ __forceinline__ uint32_t f2tf32(float f) {
    uint32_t u;
    asm("cvt.rna.tf32.f32 %0, %1;" : "=r"(u) : "f"(f));
    return u;
}
__device__ __forceinline__ void mma_tf32(float c[4], const uint32_t a[4], const uint32_t b[2]) {
    asm volatile(
        "mma.sync.aligned.m16n8k8.row.col.f32.tf32.tf32.f32 "
        "{%0,%1,%2,%3},{%4,%5,%6,%7},{%8,%9},{%0,%1,%2,%3};"
        : "+f"(c[0]), "+f"(c[1]), "+f"(c[2]), "+f"(c[3])
        : "r"(a[0]), "r"(a[1]), "r"(a[2]), "r"(a[3]), "r"(b[0]), "r"(b[1]));
}
__device__ __forceinline__ void cp_async16(void* smem, const void* g) {
    uint32_t s = (uint32_t)__cvta_generic_to_shared(smem);
    asm volatile("cp.async.cg.shared.global [%0], [%1], 16;" :: "r"(s), "l"(g));
}
#define CP_COMMIT() asm volatile("cp.async.commit_group;")
#define CP_WAIT(n)  asm volatile("cp.async.wait_group %0;" :: "n"(n))

__device__ __forceinline__ uint32_t sm_u32(const void* p) {
    return (uint32_t)__cvta_generic_to_shared(p);
}
__device__ __forceinline__ void ldsm_x4(uint32_t r[4], uint32_t addr) {
    asm volatile("ldmatrix.sync.aligned.m8n8.x4.shared.b16 {%0,%1,%2,%3}, [%4];"
                 : "=r"(r[0]), "=r"(r[1]), "=r"(r[2]), "=r"(r[3]) : "r"(addr));
}
__device__ __forceinline__ void ldsm_x2(uint32_t r[2], uint32_t addr) {
    asm volatile("ldmatrix.sync.aligned.m8n8.x2.shared.b16 {%0,%1}, [%2];"
                 : "=r"(r[0]), "=r"(r[1]) : "r"(addr));
}

// ---------------- bulk fp32 -> tf32-bit convert ----------------
__global__ void cvt_tf32_kernel(const float* __restrict__ in, float* __restrict__ out, int n4)
{
    int i = blockIdx.x * 256 + threadIdx.x;
    if (i >= n4) return;
    float4 v = ((const float4*)in)[i];
    uint4 u = make_uint4(f2tf32(v.x), f2tf32(v.y), f2tf32(v.z), f2tf32(v.w));
    ((uint4*)out)[i] = u;
}

// ---------------- positional encodings (tf32 out) ----------------
__global__ void pos_kernel(float* __restrict__ pos)
{
    int idx = blockIdx.x * blockDim.x + threadIdx.x;
    if (idx >= TTt * (DDd / 2)) return;
    int t = idx / (DDd / 2), j = idx % (DDd / 2);
    double invf = exp(((double)(-2 * j) / (double)DDd) * 9.210340371976184);
    double ang  = (double)(TTt - 1 - t) * invf;
    double kk   = floor(ang * 0.15915494309189535);
    float a = (float)(ang - kk * 6.283185307179586);
    pos[(size_t)t * DDd + j]           = __uint_as_float(f2tf32(sinf(a)));
    pos[(size_t)t * DDd + j + DDd / 2] = __uint_as_float(f2tf32(cosf(a)));
}

// ======================================================================
// Async GEMM core (R9 verified): pre-converted tf32 operands.
// ======================================================================
template<int BM, int NWN>
__device__ __forceinline__ void gemm_core_async(
    const float* __restrict__ Ag, const float* __restrict__ Bg, float* __restrict__ Cg,
    int N, int K, int lda, float alpha, const float* __restrict__ biasg, int relu,
    int cvt_out)
{
    constexpr int BN = NWN * 32;
    constexpr int NWM = 8 / NWN;
    constexpr int WM = BM / NWM;
    constexpr int MT = WM / 16;
    constexpr int BPITCH = BN + 8;
    constexpr int NA_CH = BM / 64;
    constexpr int NB_CH = BN / 64;

    __shared__ uint32_t As[2][BM][20];
    __shared__ uint32_t Bs[2][16][BPITCH];

    int tid = threadIdx.x, lane = tid & 31, warp = tid >> 5;
    int g = lane >> 2, tg = lane & 3;
    int warp_m = warp % NWM, warp_n = warp / NWM;
    int wm = warp_m * WM, wn = warp_n * 32;

    float acc[MT][4][4];
#pragma unroll
    for (int mt = 0; mt < MT; mt++)
#pragma unroll
        for (int nt = 0; nt < 4; nt++)
#pragma unroll
            for (int i = 0; i < 4; i++) acc[mt][nt][i] = 0.f;

    int ar[NA_CH], ak[NA_CH];
#pragma unroll
    for (int j = 0; j < NA_CH; j++) {
        int c = tid + j * 256;
        ar[j] = c >> 2; ak[j] = (c & 3) * 4;
    }
    int bk[NB_CH], bn[NB_CH];
#pragma unroll
    for (int j = 0; j < NB_CH; j++) {
        int c = tid + j * 256;
        if (BN == 128) { bk[j] = c >> 5; bn[j] = (c & 31) * 4; }
        else           { bk[j] = c >> 4; bn[j] = (c & 15) * 4; }
    }

    int nk = K / 16;

#pragma unroll
    for (int j = 0; j < NA_CH; j++)
        cp_async16(&As[0][ar[j]][ak[j]], Ag + (size_t)ar[j] * lda + ak[j]);
#pragma unroll
    for (int j = 0; j < NB_CH; j++)
        cp_async16(&Bs[0][bk[j]][bn[j]], Bg + (size_t)bk[j] * N + bn[j]);
    CP_COMMIT();

    for (int kt = 0; kt < nk; kt++) {
        int buf = kt & 1;
        bool more = (kt + 1 < nk);
        if (more) {
            int nb = buf ^ 1;
#pragma unroll
            for (int j = 0; j < NA_CH; j++)
                cp_async16(&As[nb][ar[j]][ak[j]],
                           Ag + (size_t)ar[j] * lda + (kt + 1) * 16 + ak[j]);
#pragma unroll
            for (int j = 0; j < NB_CH; j++)
                cp_async16(&Bs[nb][bk[j]][bn[j]],
                           Bg + (size_t)((kt + 1) * 16 + bk[j]) * N + bn[j]);
            CP_COMMIT();
            CP_WAIT(1);
        } else {
            CP_WAIT(0);
        }
        __syncthreads();

#pragma unroll
        for (int ks = 0; ks < 2; ks++) {
            uint32_t af[MT][4], bf[4][2];
#pragma unroll
            for (int mt = 0; mt < MT; mt++) {
                int row = wm + mt * 16;
                af[mt][0] = As[buf][row + g][ks * 8 + tg];
                af[mt][1] = As[buf][row + g + 8][ks * 8 + tg];
                af[mt][2] = As[buf][row + g][ks * 8 + tg + 4];
                af[mt][3] = As[buf][row + g + 8][ks * 8 + tg + 4];
            }
#pragma unroll
            for (int nt = 0; nt < 4; nt++) {
                int col = wn + nt * 8 + g;
                bf[nt][0] = Bs[buf][ks * 8 + tg][col];
                bf[nt][1] = Bs[buf][ks * 8 + tg + 4][col];
            }
#pragma unroll
            for (int mt = 0; mt < MT; mt++)
#pragma unroll
                for (int nt = 0; nt < 4; nt++) mma_tf32(acc[mt][nt], af[mt], bf[nt]);
        }
        if (more) __syncthreads();
    }

#pragma unroll
    for (int mt = 0; mt < MT; mt++) {
#pragma unroll
        for (int nt = 0; nt < 4; nt++) {
            int row = wm + mt * 16 + g;
            int col = wn + nt * 8 + tg * 2;
            float bx0 = 0.f, bx1 = 0.f;
            if (biasg) { bx0 = biasg[col]; bx1 = biasg[col + 1]; }
            float v0 = acc[mt][nt][0] * alpha + bx0;
            float v1 = acc[mt][nt][1] * alpha + bx1;
            float v2 = acc[mt][nt][2] * alpha + bx0;
            float v3 = acc[mt][nt][3] * alpha + bx1;
            if (relu) {
                v0 = fmaxf(v0, 0.f); v1 = fmaxf(v1, 0.f);
                v2 = fmaxf(v2, 0.f); v3 = fmaxf(v3, 0.f);
            }
            if (cvt_out) {
                v0 = __uint_as_float(f2tf32(v0));
                v1 = __uint_as_float(f2tf32(v1));
                v2 = __uint_as_float(f2tf32(v2));
                v3 = __uint_as_float(f2tf32(v3));
            }
            *(float2*)(Cg + (size_t)row * N + col)       = make_float2(v0, v1);
            *(float2*)(Cg + (size_t)(row + 8) * N + col) = make_float2(v2, v3);
        }
    }
}

template<int BM, int NWN>
__global__ void __launch_bounds__(256) tc_gemm_k(
    const float* __restrict__ A, const float* __restrict__ B, float* __restrict__ C,
    int N, int K, float alpha, const float* __restrict__ bias, int relu, int cvt_out)
{
    constexpr int BN = NWN * 32;
    const float* Ag = A + (size_t)blockIdx.y * BM * K;
    const float* Bg = B + (size_t)blockIdx.x * BN;
    float* Cg = C + (size_t)blockIdx.y * BM * N + (size_t)blockIdx.x * BN;
    const float* bg = bias ? bias + (size_t)blockIdx.x * BN : nullptr;
    gemm_core_async<BM, NWN>(Ag, Bg, Cg, N, K, K, alpha, bg, relu, cvt_out);
}

template<int BM, int NWN>
__global__ void __launch_bounds__(256) tc_gemm_splitk(
    const float* __restrict__ A, const float* __restrict__ B,
    float* __restrict__ C0, float* __restrict__ C1,
    int N, int K, const float* __restrict__ bias)
{
    constexpr int BN = NWN * 32;
    int z = blockIdx.z;
    int K2 = K >> 1;
    const float* Ag = A + (size_t)blockIdx.y * BM * K + (size_t)z * K2;
    const float* Bg = B + (size_t)z * K2 * N + (size_t)blockIdx.x * BN;
    float* C = z ? C1 : C0;
    float* Cg = C + (size_t)blockIdx.y * BM * N + (size_t)blockIdx.x * BN;
    const float* bg = (bias && z == 0) ? bias + (size_t)blockIdx.x * BN : nullptr;
    gemm_core_async<BM, NWN>(Ag, Bg, Cg, N, K2, K, 1.f, bg, 0, 0);
}

// grouped q/k/v/r projections (R9 verified)
__global__ void __launch_bounds__(256) grouped_qkvr(
    const float* __restrict__ hcc, const float* __restrict__ memc, const float* __restrict__ pos,
    const float* __restrict__ Wq, const float* __restrict__ Wk,
    const float* __restrict__ Wv, const float* __restrict__ Wr,
    float* __restrict__ q, float* __restrict__ k, float* __restrict__ v, float* __restrict__ r)
{
    int y = blockIdx.y;
    const float* Ag; const float* B; float* C; float alpha = 1.f; int cvt = 1;
    if (y < 8) {
        Ag = hcc + (size_t)y * 128 * DDd; B = Wq; C = q + (size_t)y * 128 * DDd;
        alpha = 0.125f; cvt = 0;
    } else if (y < 40) {
        int yy = (y < 24) ? y - 8 : y - 24;
        int row0 = yy * 128;
        int b = row0 >> 10, t0 = row0 & 1023;
        Ag = (t0 < MMm) ? memc + ((size_t)b * MMm + t0) * DDd
                        : hcc  + ((size_t)b * SSq + (t0 - MMm)) * DDd;
        if (y < 24) { B = Wk; C = k + (size_t)yy * 128 * DDd; }
        else        { B = Wv; C = v + (size_t)yy * 128 * DDd; }
    } else {
        int yy = y - 40;
        Ag = pos + (size_t)yy * 128 * DDd; B = Wr; C = r + (size_t)yy * 128 * DDd;
    }
    const float* Bg = B + (size_t)blockIdx.x * 128;
    float* Cg = C + (size_t)blockIdx.x * 128;
    gemm_core_async<128, 4>(Ag, Bg, Cg, DDd, DDd, DDd, alpha, nullptr, 0, cvt);
}

// ======================================================================
// Flash fused attention v3: warp-exclusive row softmax, 3 syncs/tile,
// K/R + V prefetch, logits/P share one smem tile.
// ======================================================================
#define SMT   32
#define TN    64
#define QPITCH 68
#define WPITCH 100
// floats: Qc 2176, Qr 2176, K 4352, R 6528, V 4352, Lt 2176, QRW 3200, stats 96
#define SMEM_ATTN_FLOATS (2*SMT*QPITCH + 64*QPITCH + 96*QPITCH + 64*QPITCH + SMT*QPITCH + SMT*WPITCH + 96)
#define SMEM_ATTN_BYTES  (SMEM_ATTN_FLOATS * 4)

__global__ void __launch_bounds__(256) fused_attn(
    const float* __restrict__ q, const float* __restrict__ k, const float* __restrict__ v,
    const float* __restrict__ r, const float* __restrict__ rwb, const float* __restrict__ rrb,
    float* __restrict__ attn)
{
    extern __shared__ float sm[];
    uint32_t* Qcb  = (uint32_t*)sm;                   // [32][68]
    uint32_t* Qrb  = Qcb + SMT * QPITCH;              // [32][68]
    uint32_t* Ktb  = Qrb + SMT * QPITCH;              // [64][68]
    uint32_t* Rwb  = Ktb + 64 * QPITCH;               // [96][68]
    uint32_t* Vtb  = Rwb + 96 * QPITCH;               // [64][68]
    float*    Lt   = (float*)(Vtb + 64 * QPITCH);     // [32][68] logits -> P tf32
    float*    QRW  = Lt + SMT * QPITCH;               // [32][100]
    float*    crow = QRW + SMT * WPITCH;              // [32]
    float*    rowm = crow + 32;                        // [32]
    float*    rowsum = rowm + 32;                      // [32]
    uint32_t* Ltb  = (uint32_t*)Lt;

    int tid = threadIdx.x, lane = tid & 31, warp = tid >> 5;
    int g = lane >> 2, tg = lane & 3;
    int s0 = (15 - blockIdx.x) * SMT;     // heavy blocks first
    int b = blockIdx.y >> 4, h = blockIdx.y & 15;

    const float* qb = q + (size_t)b * SSq * DDd + h * DKk;
    const float* kb = k + (size_t)b * TTt * DDd + h * DKk;
    const float* vb = v + (size_t)b * TTt * DDd + h * DKk;
    const float* rb = r + h * DKk;
    const float* wbv = rwb + h * DKk;
    const float* rbv = rrb + h * DKk;

    int ntiles = (s0 + 543) / 64 + 1;
    int lrow = tid >> 4, lk0 = (tid & 15) * 4;

    auto issue_KR = [&](int it) {
        if (it < ntiles) {
            int t0 = it * TN, jb = t0 - s0 + 480;
#pragma unroll
            for (int j = 0; j < 4; j++) {
                int row = lrow + j * 16;
                cp_async16(&Ktb[row * QPITCH + lk0], kb + (size_t)(t0 + row) * DDd + lk0);
            }
#pragma unroll
            for (int j = 0; j < 6; j++) {
                int row = lrow + j * 16;
                int jg = jb + row; if (jg > TTt - 1) jg = TTt - 1;
                cp_async16(&Rwb[row * QPITCH + lk0], rb + (size_t)jg * DDd + lk0);
            }
        }
        CP_COMMIT();
    };
    auto issue_V = [&](int it) {
        if (it < ntiles) {
            int t0 = it * TN;
#pragma unroll
            for (int j = 0; j < 4; j++) {
                int row = lrow + j * 16;
                cp_async16(&Vtb[row * QPITCH + lk0], vb + (size_t)(t0 + row) * DDd + lk0);
            }
        }
        CP_COMMIT();
    };

    issue_KR(0);

    // phase 1: Qc = q + rwb, Qr = q + rrb (tf32) while KR(0) flies
#pragma unroll
    for (int j = 0; j < 2; j++) {
        int c = tid + j * 256;
        int row = c >> 4, k0 = (c & 15) * 4;
        float4 qv = *(const float4*)(qb + (size_t)(s0 + row) * DDd + k0);
        float4 w4 = *(const float4*)(wbv + k0);
        float4 r4 = *(const float4*)(rbv + k0);
        Qcb[row * QPITCH + k0 + 0] = f2tf32(qv.x + w4.x);
        Qcb[row * QPITCH + k0 + 1] = f2tf32(qv.y + w4.y);
        Qcb[row * QPITCH + k0 + 2] = f2tf32(qv.z + w4.z);
        Qcb[row * QPITCH + k0 + 3] = f2tf32(qv.w + w4.w);
        Qrb[row * QPITCH + k0 + 0] = f2tf32(qv.x + r4.x);
        Qrb[row * QPITCH + k0 + 1] = f2tf32(qv.y + r4.y);
        Qrb[row * QPITCH + k0 + 2] = f2tf32(qv.z + r4.z);
        Qrb[row * QPITCH + k0 + 3] = f2tf32(qv.w + r4.w);
    }
    if (tid < 32) { rowm[tid] = -1e30f; rowsum[tid] = 0.f; }

    int wm2 = (warp & 1) * 16;
    int wn2 = (warp >> 1) * 16;
    int wn3 = (warp >> 1) * 24;
    int r1 = wm2 + g, r2 = r1 + 8;

    // softmax row ownership: warp w owns rows 4w..4w+3
    int srow = warp * 4 + (lane >> 3);
    int scol = (lane & 7) * 8;

    // ldmatrix lane address patterns (verified R10)
    int a_row = (lane & 7) + ((lane >> 3) & 1) * 8;
    int a_col = (lane >> 4) * 4;
    int b_row = (lane & 7) + ((lane >> 4) & 1) * 8;
    int b_col = ((lane >> 3) & 1) * 4;
    int c_row = lane & 7;
    int c_col = ((lane >> 3) & 1) * 4;

    uint32_t qc_a  = sm_u32(&Qcb[(wm2 + a_row) * QPITCH + a_col]);
    uint32_t qr_a  = sm_u32(&Qrb[(wm2 + a_row) * QPITCH + a_col]);
    uint32_t lt_a  = sm_u32(&Ltb[(wm2 + a_row) * QPITCH + a_col]);
    uint32_t kt_a  = sm_u32(&Ktb[(wn2 + b_row) * QPITCH + b_col]);
    uint32_t rw4_a = sm_u32(&Rwb[(wn3 + b_row) * QPITCH + b_col]);
    uint32_t rw2_a = sm_u32(&Rwb[(wn3 + 16 + c_row) * QPITCH + c_col]);

    float oacc[2][4];
#pragma unroll
    for (int nt = 0; nt < 2; nt++)
#pragma unroll
        for (int i = 0; i < 4; i++) oacc[nt][i] = 0.f;

    for (int it = 0; it < ntiles; it++) {
        int t0 = it * TN;
        CP_WAIT(0);          // KR(it) ready (all other groups already drained)
        __syncthreads();     // sync A: tiles ready; prev V/Lt reads finished

        issue_V(it);         // V(it) overlaps QK + softmax phases

        // QK content + rel MMAs
        float ca[2][4], ra[3][4];
#pragma unroll
        for (int nt = 0; nt < 2; nt++)
#pragma unroll
            for (int i = 0; i < 4; i++) ca[nt][i] = 0.f;
#pragma unroll
        for (int nt = 0; nt < 3; nt++)
#pragma unroll
            for (int i = 0; i < 4; i++) ra[nt][i] = 0.f;

#pragma unroll
        for (int k8 = 0; k8 < 64; k8 += 8) {
            uint32_t koff = k8 * 4;
            uint32_t af[4], afr[4], bk4[4], br4[4], br2[2];
            ldsm_x4(af,  qc_a + koff);
            ldsm_x4(afr, qr_a + koff);
            ldsm_x4(bk4, kt_a + koff);
            ldsm_x4(br4, rw4_a + koff);
            ldsm_x2(br2, rw2_a + koff);
            {
                uint32_t bf0[2] = {bk4[0], bk4[1]};
                uint32_t bf1[2] = {bk4[2], bk4[3]};
                mma_tf32(ca[0], af, bf0);
                mma_tf32(ca[1], af, bf1);
            }
            {
                uint32_t bf0[2] = {br4[0], br4[1]};
                uint32_t bf1[2] = {br4[2], br4[3]};
                mma_tf32(ra[0], afr, bf0);
                mma_tf32(ra[1], afr, bf1);
                mma_tf32(ra[2], afr, br2);
            }
        }
        // write content logits + rel window to smem
#pragma unroll
        for (int nt = 0; nt < 2; nt++) {
            int c0 = wn2 + nt * 8 + tg * 2;
            Lt[r1 * QPITCH + c0]     = ca[nt][0];
            Lt[r1 * QPITCH + c0 + 1] = ca[nt][1];
            Lt[r2 * QPITCH + c0]     = ca[nt][2];
            Lt[r2 * QPITCH + c0 + 1] = ca[nt][3];
        }
#pragma unroll
        for (int nt = 0; nt < 3; nt++) {
            int c0 = wn3 + nt * 8 + tg * 2;
            QRW[r1 * WPITCH + c0]     = ra[nt][0];
            QRW[r1 * WPITCH + c0 + 1] = ra[nt][1];
            QRW[r2 * WPITCH + c0]     = ra[nt][2];
            QRW[r2 * WPITCH + c0 + 1] = ra[nt][3];
        }
        __syncthreads();     // sync B: Lt + QRW ready; K/R reads done

        issue_KR(it + 1);    // prefetch next K/R

        // warp-exclusive row softmax (warp owns rows 4w..4w+3)
        {
            float4 ca4 = *(const float4*)&Lt[srow * QPITCH + scol];
            float4 cb4 = *(const float4*)&Lt[srow * QPITCH + scol + 4];
            float lv[8] = {ca4.x, ca4.y, ca4.z, ca4.w, cb4.x, cb4.y, cb4.z, cb4.w};
            const float* qr = &QRW[srow * WPITCH + scol + 31 - srow];
            int lim = MMm - t0 + s0 + srow;   // valid cols c <= lim
#pragma unroll
            for (int j = 0; j < 8; j++) {
                float lvv = lv[j] + qr[j];
                lv[j] = (scol + j <= lim) ? lvv : -1e30f;
            }
            float tmax = lv[0];
#pragma unroll
            for (int j = 1; j < 8; j++) tmax = fmaxf(tmax, lv[j]);
            tmax = fmaxf(tmax, __shfl_xor_sync(0xffffffffu, tmax, 1));
            tmax = fmaxf(tmax, __shfl_xor_sync(0xffffffffu, tmax, 2));
            tmax = fmaxf(tmax, __shfl_xor_sync(0xffffffffu, tmax, 4));
            float m_old = rowm[srow];
            float m_new = fmaxf(m_old, tmax);
            float cfac = __expf(m_old - m_new);
            float p[8], tsum = 0.f;
#pragma unroll
            for (int j = 0; j < 8; j++) {
                p[j] = __expf(lv[j] - m_new);
                tsum += p[j];
            }
            tsum += __shfl_xor_sync(0xffffffffu, tsum, 1);
            tsum += __shfl_xor_sync(0xffffffffu, tsum, 2);
            tsum += __shfl_xor_sync(0xffffffffu, tsum, 4);
            uint4 u0 = make_uint4(f2tf32(p[0]), f2tf32(p[1]), f2tf32(p[2]), f2tf32(p[3]));
            uint4 u1 = make_uint4(f2tf32(p[4]), f2tf32(p[5]), f2tf32(p[6]), f2tf32(p[7]));
            *(uint4*)&Ltb[srow * QPITCH + scol]     = u0;
            *(uint4*)&Ltb[srow * QPITCH + scol + 4] = u1;
            if ((lane & 7) == 0) {
                rowm[srow] = m_new;
                rowsum[srow] = rowsum[srow] * cfac + tsum;
                crow[srow] = cfac;
            }
        }

        CP_WAIT(1);          // V(it) done (KR(it+1) may still fly)
        __syncthreads();     // sync C: P + crow + V visible

        // rescale O, then P @ V
        float c1 = crow[r1], c2 = crow[r2];
#pragma unroll
        for (int nt = 0; nt < 2; nt++) {
            oacc[nt][0] *= c1; oacc[nt][1] *= c1;
            oacc[nt][2] *= c2; oacc[nt][3] *= c2;
        }
#pragma unroll
        for (int k8 = 0; k8 < 64; k8 += 8) {
            uint32_t af[4];
            ldsm_x4(af, lt_a + k8 * 4);
#pragma unroll
            for (int nt = 0; nt < 2; nt++) {
                uint32_t bf[2];
                int col = wn2 + nt * 8 + g;
                bf[0] = Vtb[(k8 + tg) * QPITCH + col];
                bf[1] = Vtb[(k8 + tg + 4) * QPITCH + col];
                mma_tf32(oacc[nt], af, bf);
            }
        }
    }

    __syncthreads();
    float inv1 = 1.f / rowsum[r1];
    float inv2 = 1.f / rowsum[r2];
    float* ob = attn + ((size_t)b * SSq + s0) * DDd + h * DKk;
#pragma unroll
    for (int nt = 0; nt < 2; nt++) {
        int c0 = wn2 + nt * 8 + tg * 2;
        *(float2*)(ob + (size_t)r1 * DDd + c0) = make_float2(
            __uint_as_float(f2tf32(oacc[nt][0] * inv1)),
            __uint_as_float(f2tf32(oacc[nt][1] * inv1)));
        *(float2*)(ob + (size_t)r2 * DDd + c0) = make_float2(
            __uint_as_float(f2tf32(oacc[nt][2] * inv2)),
            __uint_as_float(f2tf32(oacc[nt][3] * inv2)));
    }
}

// ---------------- residual + LayerNorm over (x0 + x1 + res), dual output ----------------
__global__ void ln_kernel2(const float* __restrict__ x0, const float* __restrict__ x1,
                           const float* __restrict__ res,
                           const float* __restrict__ g, const float* __restrict__ b,
                           float* __restrict__ out, float* __restrict__ outc)
{
    int row = blockIdx.x;
    const float* xr0 = x0 + (size_t)row * DDd;
    const float* xr1 = x1 + (size_t)row * DDd;
    const float* rr  = res + (size_t)row * DDd;
    __shared__ float redA[33], redB[33];
    int tid = threadIdx.x;

    float loc[4];
    float s1 = 0.f, s2 = 0.f;
#pragma unroll
    for (int i = 0; i < 4; i++) {
        int d = tid + i * 256;
        float v = xr0[d] + xr1[d] + rr[d];
        loc[i] = v;
        s1 += v;
        s2 += v * v;
    }
#pragma unroll
    for (int o = 16; o; o >>= 1) {
        s1 += __shfl_xor_sync(0xffffffffu, s1, o);
        s2 += __shfl_xor_sync(0xffffffffu, s2, o);
    }
    if ((tid & 31) == 0) { redA[tid >> 5] = s1; redB[tid >> 5] = s2; }
    __syncthreads();
    if (tid < 32) {
        float a = (tid < 8) ? redA[tid] : 0.f;
        float c = (tid < 8) ? redB[tid] : 0.f;
#pragma unroll
        for (int o = 4; o; o >>= 1) {
            a += __shfl_xor_sync(0xffffffffu, a, o);
            c += __shfl_xor_sync(0xffffffffu, c, o);
        }
        if (tid == 0) { redA[32] = a; redB[32] = c; }
    }
    __syncthreads();
    float mu  = redA[32] * (1.f / DDd);
    float var = redB[32] * (1.f / DDd) - mu * mu;
    float rstd = rsqrtf(var + 1e-5f);
#pragma unroll
    for (int i = 0; i < 4; i++) {
        int d = tid + i * 256;
        float o = (loc[i] - mu) * rstd * g[d] + b[d];
        out[(size_t)row * DDd + d] = o;
        if (outc) outc[(size_t)row * DDd + d] = __uint_as_float(f2tf32(o));
    }
}

// ---------------- host-side orchestration ----------------
extern "C" void kernel_launch(void* const* d_in, const int* in_sizes, int n_in,
                              void* d_out, int out_size)
{
    const float* x      = (const float*)d_in[0];
    const float* memory = (const float*)d_in[1];
    const float* Wq  = (const float*)d_in[2];
    const float* Wk  = (const float*)d_in[3];
    const float* Wv  = (const float*)d_in[4];
    const float* Wr  = (const float*)d_in[5];
    const float* Wo  = (const float*)d_in[6];
    const float* rwb = (const float*)d_in[7];
    const float* rrb = (const float*)d_in[8];
    const float* ln1g = (const float*)d_in[9];
    const float* ln1b = (const float*)d_in[10];
    const float* ln2g = (const float*)d_in[11];
    const float* ln2b = (const float*)d_in[12];
    const float* W1  = (const float*)d_in[13];
    const float* b1  = (const float*)d_in[14];
    const float* W2  = (const float*)d_in[15];
    const float* b2  = (const float*)d_in[16];
    float* out = (float*)d_out;

    float *pos, *q, *k, *v, *r, *attn, *tmp, *tmp2, *ff, *h, *hc, *h1, *h1c;
    float *wqc, *wkc, *wvc, *wrc, *woc, *w1c, *w2c, *memc, *xc;
    cudaGetSymbolAddress((void**)&pos,  g_pos);
    cudaGetSymbolAddress((void**)&q,    g_q);
    cudaGetSymbolAddress((void**)&k,    g_k);
    cudaGetSymbolAddress((void**)&v,    g_v);
    cudaGetSymbolAddress((void**)&r,    g_r);
    cudaGetSymbolAddress((void**)&attn, g_attn);
    cudaGetSymbolAddress((void**)&tmp,  g_tmp);
    cudaGetSymbolAddress((void**)&tmp2, g_tmp2);
    cudaGetSymbolAddress((void**)&ff,   g_ff);
    cudaGetSymbolAddress((void**)&h,    g_h);
    cudaGetSymbolAddress((void**)&hc,   g_hc);
    cudaGetSymbolAddress((void**)&h1,   g_h1);
    cudaGetSymbolAddress((void**)&h1c,  g_h1c);
    cudaGetSymbolAddress((void**)&wqc,  g_wqc);
    cudaGetSymbolAddress((void**)&wkc,  g_wkc);
    cudaGetSymbolAddress((void**)&wvc,  g_wvc);
    cudaGetSymbolAddress((void**)&wrc,  g_wrc);
    cudaGetSymbolAddress((void**)&woc,  g_woc);
    cudaGetSymbolAddress((void**)&w1c,  g_w1c);
    cudaGetSymbolAddress((void**)&w2c,  g_w2c);
    cudaGetSymbolAddress((void**)&memc, g_memc);
    cudaGetSymbolAddress((void**)&xc,   g_xc);

    cudaFuncSetAttribute(fused_attn, cudaFuncAttributeMaxDynamicSharedMemorySize,
                         SMEM_ATTN_BYTES);

    // one-shot converts (per-tensor grids, R9-verified form)
    auto cvt = [&](const float* in, float* o, size_t n) {
        int n4 = (int)(n / 4);
        cvt_tf32_kernel<<<(n4 + 255) / 256, 256>>>(in, o, n4);
    };
    cvt(Wq, wqc, (size_t)LL * DDd * DDd);
    cvt(Wk, wkc, (size_t)LL * DDd * DDd);
    cvt(Wv, wvc, (size_t)LL * DDd * DDd);
    cvt(Wr, wrc, (size_t)LL * DDd * DDd);
    cvt(Wo, woc, (size_t)LL * DDd * DDd);
    cvt(W1, w1c, (size_t)LL * DDd * FFf);
    cvt(W2, w2c, (size_t)LL * FFf * DDd);
    cvt(memory, memc, (size_t)LL * BB * MMm * DDd);
    cvt(x, xc, (size_t)BB * SSq * DDd);

    pos_kernel<<<(TTt * (DDd / 2) + 255) / 256, 256>>>(pos);

    const float* hcur  = x;
    const float* hcurc = xc;
    for (int l = 0; l < LL; l++) {
        dim3 gG(DDd / 128, 48);
        grouped_qkvr<<<gG, 256>>>(hcurc, memc + (size_t)l * BB * MMm * DDd, pos,
                                  wqc + (size_t)l * DDd * DDd, wkc + (size_t)l * DDd * DDd,
                                  wvc + (size_t)l * DDd * DDd, wrc + (size_t)l * DDd * DDd,
                                  q, k, v, r);

        dim3 gA(SSq / SMT, BB * HHh);
        fused_attn<<<gA, 256, SMEM_ATTN_BYTES>>>(
            q, k, v, r, rwb + (size_t)l * HHh * DKk, rrb + (size_t)l * HHh * DKk, attn);

        dim3 gO(DDd / 128, (BB * SSq) / 64, 2);
        tc_gemm_splitk<64, 4><<<gO, 256>>>(attn, woc + (size_t)l * DDd * DDd,
                                           tmp, tmp2, DDd, DDd, nullptr);
        ln_kernel2<<<BB * SSq, 256>>>(tmp, tmp2, hcur,
                                      ln1g + l * DDd, ln1b + l * DDd, h1, h1c);

        dim3 gF1(FFf / 128, (BB * SSq) / 128);
        tc_gemm_k<128, 4><<<gF1, 256>>>(h1c, w1c + (size_t)l * DDd * FFf, ff,
                                        FFf, DDd, 1.f, b1 + l * FFf, 1, 1);
        dim3 gF2(DDd / 128, (BB * SSq) / 64, 2);
        tc_gemm_splitk<64, 4><<<gF2, 256>>>(ff, w2c + (size_t)l * FFf * DDd,
                                            tmp, tmp2, DDd, FFf, b2 + l * DDd);

        if (l == LL - 1) {
            ln_kernel2<<<BB * SSq, 256>>>(tmp, tmp2, h1,
                                          ln2g + l * DDd, ln2b + l * DDd, out, nullptr);
        } else {
            ln_kernel2<<<BB * SSq, 256>>>(tmp, tmp2, h1,
                                          ln2g + l * DDd, ln2b + l * DDd, h, hc);
            hcur = h;
            hcurc = hc;
        }
    }
}

// round 12
// speedup vs baseline: 1.0249x; 1.0225x over previous
#include <cuda_runtime.h>
#include <math.h>
#include <stdint.h>

// Problem dims
#define LL  4
#define BB  2
#define SSq 512
#define MMm 512
#define DDd 1024
#define HHh 16
#define DKk 64
#define FFf 4096
#define TTt (SSq + MMm)   // 1024

// ---------------- scratch ----------------
__device__ float g_pos[TTt * DDd];        // tf32 bits
__device__ float g_q  [BB * SSq * DDd];   // fp32 (biases added in fused_attn)
__device__ float g_k  [BB * TTt * DDd];   // tf32 bits
__device__ float g_v  [BB * TTt * DDd];   // tf32 bits
__device__ float g_r  [TTt * DDd];        // tf32 bits
__device__ float g_attn[BB * SSq * DDd];  // tf32 bits
__device__ float g_tmp [BB * SSq * DDd];  // attn O-partial z=0 / o-proj partial
__device__ float g_tmp2[BB * SSq * DDd];  // attn O-partial z=1 / o-proj partial
__device__ float g_pm [2 * BB * HHh * SSq];
__device__ float g_ps [2 * BB * HHh * SSq];
__device__ float g_ff  [BB * SSq * FFf];  // tf32 bits
__device__ float g_h   [BB * SSq * DDd];  // fp32 residual
__device__ float g_hc  [BB * SSq * DDd];  // tf32 copy
__device__ float g_h1  [BB * SSq * DDd];  // fp32 residual
__device__ float g_h1c [BB * SSq * DDd];  // tf32 copy
// pre-converted operands (tf32 bits)
__device__ float g_wqc[LL * DDd * DDd];
__device__ float g_wkc[LL * DDd * DDd];
__device__ float g_wvc[LL * DDd * DDd];
__device__ float g_wrc[LL * DDd * DDd];
__device__ float g_woc[LL * DDd * DDd];
__device__ float g_w1c[LL * DDd * FFf];
__device__ float g_w2c[LL * FFf * DDd];
__device__ float g_memc[LL * BB * MMm * DDd];
__device__ float g_xc  [BB * SSq * DDd];

// ---------------- PTX helpers ----------------
__device__ __forceinline__ uint32_t f2tf32(float f) {
    uint32_t u;
    asm("cvt.rna.tf32.f32 %0, %1;" : "=r"(u) : "f"(f));
    return u;
}
__device__ __forceinline__ void mma_tf32(float c[4], const uint32_t a[4], const uint32_t b[2]) {
    asm volatile(
        "mma.sync.aligned.m16n8k8.row.col.f32.tf32.tf32.f32 "
        "{%0,%1,%2,%3},{%4,%5,%6,%7},{%8,%9},{%0,%1,%2,%3};"
        : "+f"(c[0]), "+f"(c[1]), "+f"(c[2]), "+f"(c[3])
        : "r"(a[0]), "r"(a[1]), "r"(a[2]), "r"(a[3]), "r"(b[0]), "r"(b[1]));
}
__device__ __forceinline__ void cp_async16(void* smem, const void* g) {
    uint32_t s = (uint32_t)__cvta_generic_to_shared(smem);
    asm volatile("cp.async.cg.shared.global [%0], [%1], 16;" :: "r"(s), "l"(g));
}
#define CP_COMMIT() asm volatile("cp.async.commit_group;")
#define CP_WAIT(n)  asm volatile("cp.async.wait_group %0;" :: "n"(n))

__device__ __forceinline__ uint32_t sm_u32(const void* p) {
    return (uint32_t)__cvta_generic_to_shared(p);
}
__device__ __forceinline__ void ldsm_x4(uint32_t r[4], uint32_t addr) {
    asm volatile("ldmatrix.sync.aligned.m8n8.x4.shared.b16 {%0,%1,%2,%3}, [%4];"
                 : "=r"(r[0]), "=r"(r[1]), "=r"(r[2]), "=r"(r[3]) : "r"(addr));
}
__device__ __forceinline__ void ldsm_x2(uint32_t r[2], uint32_t addr) {
    asm volatile("ldmatrix.sync.aligned.m8n8.x2.shared.b16 {%0,%1}, [%2];"
                 : "=r"(r[0]), "=r"(r[1]) : "r"(addr));
}

// ---------------- bulk fp32 -> tf32-bit convert ----------------
__global__ void cvt_tf32_kernel(const float* __restrict__ in, float* __restrict__ out, int n4)
{
    int i = blockIdx.x * 256 + threadIdx.x;
    if (i >= n4) return;
    float4 v = ((const float4*)in)[i];
    uint4 u = make_uint4(f2tf32(v.x), f2tf32(v.y), f2tf32(v.z), f2tf32(v.w));
    ((uint4*)out)[i] = u;
}

// ---------------- positional encodings (tf32 out) ----------------
__global__ void pos_kernel(float* __restrict__ pos)
{
    int idx = blockIdx.x * blockDim.x + threadIdx.x;
    if (idx >= TTt * (DDd / 2)) return;
    int t = idx / (DDd / 2), j = idx % (DDd / 2);
    double invf = exp(((double)(-2 * j) / (double)DDd) * 9.210340371976184);
    double ang  = (double)(TTt - 1 - t) * invf;
    double kk   = floor(ang * 0.15915494309189535);
    float a = (float)(ang - kk * 6.283185307179586);
    pos[(size_t)t * DDd + j]           = __uint_as_float(f2tf32(sinf(a)));
    pos[(size_t)t * DDd + j + DDd / 2] = __uint_as_float(f2tf32(cosf(a)));
}

// ======================================================================
// Async GEMM core (R9 verified): pre-converted tf32 operands.
// ======================================================================
template<int BM, int NWN>
__device__ __forceinline__ void gemm_core_async(
    const float* __restrict__ Ag, const float* __restrict__ Bg, float* __restrict__ Cg,
    int N, int K, int lda, float alpha, const float* __restrict__ biasg, int relu,
    int cvt_out)
{
    constexpr int BN = NWN * 32;
    constexpr int NWM = 8 / NWN;
    constexpr int WM = BM / NWM;
    constexpr int MT = WM / 16;
    constexpr int BPITCH = BN + 8;
    constexpr int NA_CH = BM / 64;
    constexpr int NB_CH = BN / 64;

    __shared__ uint32_t As[2][BM][20];
    __shared__ uint32_t Bs[2][16][BPITCH];

    int tid = threadIdx.x, lane = tid & 31, warp = tid >> 5;
    int g = lane >> 2, tg = lane & 3;
    int warp_m = warp % NWM, warp_n = warp / NWM;
    int wm = warp_m * WM, wn = warp_n * 32;

    float acc[MT][4][4];
#pragma unroll
    for (int mt = 0; mt < MT; mt++)
#pragma unroll
        for (int nt = 0; nt < 4; nt++)
#pragma unroll
            for (int i = 0; i < 4; i++) acc[mt][nt][i] = 0.f;

    int ar[NA_CH], ak[NA_CH];
#pragma unroll
    for (int j = 0; j < NA_CH; j++) {
        int c = tid + j * 256;
        ar[j] = c >> 2; ak[j] = (c & 3) * 4;
    }
    int bk[NB_CH], bn[NB_CH];
#pragma unroll
    for (int j = 0; j < NB_CH; j++) {
        int c = tid + j * 256;
        if (BN == 128) { bk[j] = c >> 5; bn[j] = (c & 31) * 4; }
        else           { bk[j] = c >> 4; bn[j] = (c & 15) * 4; }
    }

    int nk = K / 16;

#pragma unroll
    for (int j = 0; j < NA_CH; j++)
        cp_async16(&As[0][ar[j]][ak[j]], Ag + (size_t)ar[j] * lda + ak[j]);
#pragma unroll
    for (int j = 0; j < NB_CH; j++)
        cp_async16(&Bs[0][bk[j]][bn[j]], Bg + (size_t)bk[j] * N + bn[j]);
    CP_COMMIT();

    for (int kt = 0; kt < nk; kt++) {
        int buf = kt & 1;
        bool more = (kt + 1 < nk);
        if (more) {
            int nb = buf ^ 1;
#pragma unroll
            for (int j = 0; j < NA_CH; j++)
                cp_async16(&As[nb][ar[j]][ak[j]],
                           Ag + (size_t)ar[j] * lda + (kt + 1) * 16 + ak[j]);
#pragma unroll
            for (int j = 0; j < NB_CH; j++)
                cp_async16(&Bs[nb][bk[j]][bn[j]],
                           Bg + (size_t)((kt + 1) * 16 + bk[j]) * N + bn[j]);
            CP_COMMIT();
            CP_WAIT(1);
        } else {
            CP_WAIT(0);
        }
        __syncthreads();

#pragma unroll
        for (int ks = 0; ks < 2; ks++) {
            uint32_t af[MT][4], bf[4][2];
#pragma unroll
            for (int mt = 0; mt < MT; mt++) {
                int row = wm + mt * 16;
                af[mt][0] = As[buf][row + g][ks * 8 + tg];
                af[mt][1] = As[buf][row + g + 8][ks * 8 + tg];
                af[mt][2] = As[buf][row + g][ks * 8 + tg + 4];
                af[mt][3] = As[buf][row + g + 8][ks * 8 + tg + 4];
            }
#pragma unroll
            for (int nt = 0; nt < 4; nt++) {
                int col = wn + nt * 8 + g;
                bf[nt][0] = Bs[buf][ks * 8 + tg][col];
                bf[nt][1] = Bs[buf][ks * 8 + tg + 4][col];
            }
#pragma unroll
            for (int mt = 0; mt < MT; mt++)
#pragma unroll
                for (int nt = 0; nt < 4; nt++) mma_tf32(acc[mt][nt], af[mt], bf[nt]);
        }
        if (more) __syncthreads();
    }

#pragma unroll
    for (int mt = 0; mt < MT; mt++) {
#pragma unroll
        for (int nt = 0; nt < 4; nt++) {
            int row = wm + mt * 16 + g;
            int col = wn + nt * 8 + tg * 2;
            float bx0 = 0.f, bx1 = 0.f;
            if (biasg) { bx0 = biasg[col]; bx1 = biasg[col + 1]; }
            float v0 = acc[mt][nt][0] * alpha + bx0;
            float v1 = acc[mt][nt][1] * alpha + bx1;
            float v2 = acc[mt][nt][2] * alpha + bx0;
            float v3 = acc[mt][nt][3] * alpha + bx1;
            if (relu) {
                v0 = fmaxf(v0, 0.f); v1 = fmaxf(v1, 0.f);
                v2 = fmaxf(v2, 0.f); v3 = fmaxf(v3, 0.f);
            }
            if (cvt_out) {
                v0 = __uint_as_float(f2tf32(v0));
                v1 = __uint_as_float(f2tf32(v1));
                v2 = __uint_as_float(f2tf32(v2));
                v3 = __uint_as_float(f2tf32(v3));
            }
            *(float2*)(Cg + (size_t)row * N + col)       = make_float2(v0, v1);
            *(float2*)(Cg + (size_t)(row + 8) * N + col) = make_float2(v2, v3);
        }
    }
}

template<int BM, int NWN>
__global__ void __launch_bounds__(256) tc_gemm_k(
    const float* __restrict__ A, const float* __restrict__ B, float* __restrict__ C,
    int N, int K, float alpha, const float* __restrict__ bias, int relu, int cvt_out)
{
    constexpr int BN = NWN * 32;
    const float* Ag = A + (size_t)blockIdx.y * BM * K;
    const float* Bg = B + (size_t)blockIdx.x * BN;
    float* Cg = C + (size_t)blockIdx.y * BM * N + (size_t)blockIdx.x * BN;
    const float* bg = bias ? bias + (size_t)blockIdx.x * BN : nullptr;
    gemm_core_async<BM, NWN>(Ag, Bg, Cg, N, K, K, alpha, bg, relu, cvt_out);
}

template<int BM, int NWN>
__global__ void __launch_bounds__(256) tc_gemm_splitk(
    const float* __restrict__ A, const float* __restrict__ B,
    float* __restrict__ C0, float* __restrict__ C1,
    int N, int K, const float* __restrict__ bias)
{
    constexpr int BN = NWN * 32;
    int z = blockIdx.z;
    int K2 = K >> 1;
    const float* Ag = A + (size_t)blockIdx.y * BM * K + (size_t)z * K2;
    const float* Bg = B + (size_t)z * K2 * N + (size_t)blockIdx.x * BN;
    float* C = z ? C1 : C0;
    float* Cg = C + (size_t)blockIdx.y * BM * N + (size_t)blockIdx.x * BN;
    const float* bg = (bias && z == 0) ? bias + (size_t)blockIdx.x * BN : nullptr;
    gemm_core_async<BM, NWN>(Ag, Bg, Cg, N, K2, K, 1.f, bg, 0, 0);
}

// grouped q/k/v/r projections (R9 verified)
__global__ void __launch_bounds__(256) grouped_qkvr(
    const float* __restrict__ hcc, const float* __restrict__ memc, const float* __restrict__ pos,
    const float* __restrict__ Wq, const float* __restrict__ Wk,
    const float* __restrict__ Wv, const float* __restrict__ Wr,
    float* __restrict__ q, float* __restrict__ k, float* __restrict__ v, float* __restrict__ r)
{
    int y = blockIdx.y;
    const float* Ag; const float* B; float* C; float alpha = 1.f; int cvt = 1;
    if (y < 8) {
        Ag = hcc + (size_t)y * 128 * DDd; B = Wq; C = q + (size_t)y * 128 * DDd;
        alpha = 0.125f; cvt = 0;
    } else if (y < 40) {
        int yy = (y < 24) ? y - 8 : y - 24;
        int row0 = yy * 128;
        int b = row0 >> 10, t0 = row0 & 1023;
        Ag = (t0 < MMm) ? memc + ((size_t)b * MMm + t0) * DDd
                        : hcc  + ((size_t)b * SSq + (t0 - MMm)) * DDd;
        if (y < 24) { B = Wk; C = k + (size_t)yy * 128 * DDd; }
        else        { B = Wv; C = v + (size_t)yy * 128 * DDd; }
    } else {
        int yy = y - 40;
        Ag = pos + (size_t)yy * 128 * DDd; B = Wr; C = r + (size_t)yy * 128 * DDd;
    }
    const float* Bg = B + (size_t)blockIdx.x * 128;
    float* Cg = C + (size_t)blockIdx.x * 128;
    gemm_core_async<128, 4>(Ag, Bg, Cg, DDd, DDd, DDd, alpha, nullptr, 0, cvt);
}

// ======================================================================
// Flash fused attention, split over T (z = blockIdx.z selects the tile
// half). Writes UNNORMALIZED O partial + per-row (m, sum) stats.
// ======================================================================
#define SMT   32
#define TN    64
#define QPITCH 68
#define WPITCH 100
#define SMEM_ATTN_FLOATS (2*SMT*QPITCH + 64*QPITCH + 96*QPITCH + 64*QPITCH + SMT*QPITCH + SMT*WPITCH + 96)
#define SMEM_ATTN_BYTES  (SMEM_ATTN_FLOATS * 4)

__global__ void __launch_bounds__(256) fused_attn_split(
    const float* __restrict__ q, const float* __restrict__ k, const float* __restrict__ v,
    const float* __restrict__ r, const float* __restrict__ rwb, const float* __restrict__ rrb,
    float* __restrict__ o0, float* __restrict__ o1,
    float* __restrict__ pm, float* __restrict__ ps)
{
    extern __shared__ float sm[];
    uint32_t* Qcb  = (uint32_t*)sm;
    uint32_t* Qrb  = Qcb + SMT * QPITCH;
    uint32_t* Ktb  = Qrb + SMT * QPITCH;
    uint32_t* Rwb  = Ktb + 64 * QPITCH;
    uint32_t* Vtb  = Rwb + 96 * QPITCH;
    float*    Lt   = (float*)(Vtb + 64 * QPITCH);
    float*    QRW  = Lt + SMT * QPITCH;
    float*    crow = QRW + SMT * WPITCH;
    float*    rowm = crow + 32;
    float*    rowsum = rowm + 32;
    uint32_t* Ltb  = (uint32_t*)Lt;

    int tid = threadIdx.x, lane = tid & 31, warp = tid >> 5;
    int g = lane >> 2, tg = lane & 3;
    int s0 = (15 - blockIdx.x) * SMT;
    int b = blockIdx.y >> 4, h = blockIdx.y & 15;
    int z = blockIdx.z;

    const float* qb = q + (size_t)b * SSq * DDd + h * DKk;
    const float* kb = k + (size_t)b * TTt * DDd + h * DKk;
    const float* vb = v + (size_t)b * TTt * DDd + h * DKk;
    const float* rb = r + h * DKk;
    const float* wbv = rwb + h * DKk;
    const float* rbv = rrb + h * DKk;

    int ntiles = (s0 + 543) / 64 + 1;
    int nt2 = ntiles >> 1;
    int tbeg = z ? nt2 : 0;
    int tend = z ? ntiles : nt2;

    int lrow = tid >> 4, lk0 = (tid & 15) * 4;

    auto issue_KR = [&](int it) {
        if (it < tend) {
            int t0 = it * TN, jb = t0 - s0 + 480;
#pragma unroll
            for (int j = 0; j < 4; j++) {
                int row = lrow + j * 16;
                cp_async16(&Ktb[row * QPITCH + lk0], kb + (size_t)(t0 + row) * DDd + lk0);
            }
#pragma unroll
            for (int j = 0; j < 6; j++) {
                int row = lrow + j * 16;
                int jg = jb + row;
                if (jg > TTt - 1) jg = TTt - 1;
                if (jg < 0) jg = 0;
                cp_async16(&Rwb[row * QPITCH + lk0], rb + (size_t)jg * DDd + lk0);
            }
        }
        CP_COMMIT();
    };
    auto issue_V = [&](int it) {
        if (it < tend) {
            int t0 = it * TN;
#pragma unroll
            for (int j = 0; j < 4; j++) {
                int row = lrow + j * 16;
                cp_async16(&Vtb[row * QPITCH + lk0], vb + (size_t)(t0 + row) * DDd + lk0);
            }
        }
        CP_COMMIT();
    };

    issue_KR(tbeg);

    // phase 1: Qc = q + rwb, Qr = q + rrb (tf32) while KR(tbeg) flies
#pragma unroll
    for (int j = 0; j < 2; j++) {
        int c = tid + j * 256;
        int row = c >> 4, k0 = (c & 15) * 4;
        float4 qv = *(const float4*)(qb + (size_t)(s0 + row) * DDd + k0);
        float4 w4 = *(const float4*)(wbv + k0);
        float4 r4 = *(const float4*)(rbv + k0);
        Qcb[row * QPITCH + k0 + 0] = f2tf32(qv.x + w4.x);
        Qcb[row * QPITCH + k0 + 1] = f2tf32(qv.y + w4.y);
        Qcb[row * QPITCH + k0 + 2] = f2tf32(qv.z + w4.z);
        Qcb[row * QPITCH + k0 + 3] = f2tf32(qv.w + w4.w);
        Qrb[row * QPITCH + k0 + 0] = f2tf32(qv.x + r4.x);
        Qrb[row * QPITCH + k0 + 1] = f2tf32(qv.y + r4.y);
        Qrb[row * QPITCH + k0 + 2] = f2tf32(qv.z + r4.z);
        Qrb[row * QPITCH + k0 + 3] = f2tf32(qv.w + r4.w);
    }
    if (tid < 32) { rowm[tid] = -1e30f; rowsum[tid] = 0.f; }

    int wm2 = (warp & 1) * 16;
    int wn2 = (warp >> 1) * 16;
    int wn3 = (warp >> 1) * 24;
    int r1 = wm2 + g, r2 = r1 + 8;

    int srow = warp * 4 + (lane >> 3);
    int scol = (lane & 7) * 8;

    int a_row = (lane & 7) + ((lane >> 3) & 1) * 8;
    int a_col = (lane >> 4) * 4;
    int b_row = (lane & 7) + ((lane >> 4) & 1) * 8;
    int b_col = ((lane >> 3) & 1) * 4;
    int c_row = lane & 7;
    int c_col = ((lane >> 3) & 1) * 4;

    uint32_t qc_a  = sm_u32(&Qcb[(wm2 + a_row) * QPITCH + a_col]);
    uint32_t qr_a  = sm_u32(&Qrb[(wm2 + a_row) * QPITCH + a_col]);
    uint32_t lt_a  = sm_u32(&Ltb[(wm2 + a_row) * QPITCH + a_col]);
    uint32_t kt_a  = sm_u32(&Ktb[(wn2 + b_row) * QPITCH + b_col]);
    uint32_t rw4_a = sm_u32(&Rwb[(wn3 + b_row) * QPITCH + b_col]);
    uint32_t rw2_a = sm_u32(&Rwb[(wn3 + 16 + c_row) * QPITCH + c_col]);

    float oacc[2][4];
#pragma unroll
    for (int nt = 0; nt < 2; nt++)
#pragma unroll
        for (int i = 0; i < 4; i++) oacc[nt][i] = 0.f;

    for (int it = tbeg; it < tend; it++) {
        int t0 = it * TN;
        CP_WAIT(0);
        __syncthreads();     // sync A

        issue_V(it);

        float ca[2][4], ra[3][4];
#pragma unroll
        for (int nt = 0; nt < 2; nt++)
#pragma unroll
            for (int i = 0; i < 4; i++) ca[nt][i] = 0.f;
#pragma unroll
        for (int nt = 0; nt < 3; nt++)
#pragma unroll
            for (int i = 0; i < 4; i++) ra[nt][i] = 0.f;

#pragma unroll
        for (int k8 = 0; k8 < 64; k8 += 8) {
            uint32_t koff = k8 * 4;
            uint32_t af[4], afr[4], bk4[4], br4[4], br2[2];
            ldsm_x4(af,  qc_a + koff);
            ldsm_x4(afr, qr_a + koff);
            ldsm_x4(bk4, kt_a + koff);
            ldsm_x4(br4, rw4_a + koff);
            ldsm_x2(br2, rw2_a + koff);
            {
                uint32_t bf0[2] = {bk4[0], bk4[1]};
                uint32_t bf1[2] = {bk4[2], bk4[3]};
                mma_tf32(ca[0], af, bf0);
                mma_tf32(ca[1], af, bf1);
            }
            {
                uint32_t bf0[2] = {br4[0], br4[1]};
                uint32_t bf1[2] = {br4[2], br4[3]};
                mma_tf32(ra[0], afr, bf0);
                mma_tf32(ra[1], afr, bf1);
                mma_tf32(ra[2], afr, br2);
            }
        }
#pragma unroll
        for (int nt = 0; nt < 2; nt++) {
            int c0 = wn2 + nt * 8 + tg * 2;
            Lt[r1 * QPITCH + c0]     = ca[nt][0];
            Lt[r1 * QPITCH + c0 + 1] = ca[nt][1];
            Lt[r2 * QPITCH + c0]     = ca[nt][2];
            Lt[r2 * QPITCH + c0 + 1] = ca[nt][3];
        }
#pragma unroll
        for (int nt = 0; nt < 3; nt++) {
            int c0 = wn3 + nt * 8 + tg * 2;
            QRW[r1 * WPITCH + c0]     = ra[nt][0];
            QRW[r1 * WPITCH + c0 + 1] = ra[nt][1];
            QRW[r2 * WPITCH + c0]     = ra[nt][2];
            QRW[r2 * WPITCH + c0 + 1] = ra[nt][3];
        }
        __syncthreads();     // sync B

        issue_KR(it + 1);

        // warp-exclusive row softmax
        {
            float4 ca4 = *(const float4*)&Lt[srow * QPITCH + scol];
            float4 cb4 = *(const float4*)&Lt[srow * QPITCH + scol + 4];
            float lv[8] = {ca4.x, ca4.y, ca4.z, ca4.w, cb4.x, cb4.y, cb4.z, cb4.w};
            const float* qr = &QRW[srow * WPITCH + scol + 31 - srow];
            int lim = MMm - t0 + s0 + srow;
#pragma unroll
            for (int j = 0; j < 8; j++) {
                float lvv = lv[j] + qr[j];
                lv[j] = (scol + j <= lim) ? lvv : -1e30f;
            }
            float tmax = lv[0];
#pragma unroll
            for (int j = 1; j < 8; j++) tmax = fmaxf(tmax, lv[j]);
            tmax = fmaxf(tmax, __shfl_xor_sync(0xffffffffu, tmax, 1));
            tmax = fmaxf(tmax, __shfl_xor_sync(0xffffffffu, tmax, 2));
            tmax = fmaxf(tmax, __shfl_xor_sync(0xffffffffu, tmax, 4));
            float m_old = rowm[srow];
            float m_new = fmaxf(m_old, tmax);
            float cfac = __expf(m_old - m_new);
            float p[8], tsum = 0.f;
#pragma unroll
            for (int j = 0; j < 8; j++) {
                p[j] = __expf(lv[j] - m_new);
                tsum += p[j];
            }
            tsum += __shfl_xor_sync(0xffffffffu, tsum, 1);
            tsum += __shfl_xor_sync(0xffffffffu, tsum, 2);
            tsum += __shfl_xor_sync(0xffffffffu, tsum, 4);
            uint4 u0 = make_uint4(f2tf32(p[0]), f2tf32(p[1]), f2tf32(p[2]), f2tf32(p[3]));
            uint4 u1 = make_uint4(f2tf32(p[4]), f2tf32(p[5]), f2tf32(p[6]), f2tf32(p[7]));
            *(uint4*)&Ltb[srow * QPITCH + scol]     = u0;
            *(uint4*)&Ltb[srow * QPITCH + scol + 4] = u1;
            if ((lane & 7) == 0) {
                rowm[srow] = m_new;
                rowsum[srow] = rowsum[srow] * cfac + tsum;
                crow[srow] = cfac;
            }
        }

        CP_WAIT(1);
        __syncthreads();     // sync C

        float c1 = crow[r1], c2 = crow[r2];
#pragma unroll
        for (int nt = 0; nt < 2; nt++) {
            oacc[nt][0] *= c1; oacc[nt][1] *= c1;
            oacc[nt][2] *= c2; oacc[nt][3] *= c2;
        }
#pragma unroll
        for (int k8 = 0; k8 < 64; k8 += 8) {
            uint32_t af[4];
            ldsm_x4(af, lt_a + k8 * 4);
#pragma unroll
            for (int nt = 0; nt < 2; nt++) {
                uint32_t bf[2];
                int col = wn2 + nt * 8 + g;
                bf[0] = Vtb[(k8 + tg) * QPITCH + col];
                bf[1] = Vtb[(k8 + tg + 4) * QPITCH + col];
                mma_tf32(oacc[nt], af, bf);
            }
        }
    }

    __syncthreads();
    // write unnormalized O partial + row stats
    float* oz = (z ? o1 : o0) + ((size_t)b * SSq + s0) * DDd + h * DKk;
#pragma unroll
    for (int nt = 0; nt < 2; nt++) {
        int c0 = wn2 + nt * 8 + tg * 2;
        *(float2*)(oz + (size_t)r1 * DDd + c0) = make_float2(oacc[nt][0], oacc[nt][1]);
        *(float2*)(oz + (size_t)r2 * DDd + c0) = make_float2(oacc[nt][2], oacc[nt][3]);
    }
    if (warp < 2 && tg == 0) {
        int zoff = z * (BB * HHh * SSq);
        int base = blockIdx.y * SSq + s0;
        pm[zoff + base + r1] = rowm[r1];
        ps[zoff + base + r1] = rowsum[r1];
        pm[zoff + base + r2] = rowm[r2];
        ps[zoff + base + r2] = rowsum[r2];
    }
}

// ---------------- combine split-attention partials -> attn (tf32 bits) ---
__global__ void attn_combine(const float* __restrict__ o0, const float* __restrict__ o1,
                             const float* __restrict__ pm, const float* __restrict__ ps,
                             float* __restrict__ attn)
{
    int i = blockIdx.x * 256 + threadIdx.x;     // float4 index
    if (i >= (BB * SSq * DDd) / 4) return;
    int e = i * 4;
    int d = e & (DDd - 1);
    int h = d >> 6;
    int s = (e >> 10) & (SSq - 1);
    int b = e >> 19;
    int row = (b * HHh + h) * SSq + s;
    float m0 = pm[row],  m1 = pm[BB * HHh * SSq + row];
    float s0v = ps[row], s1v = ps[BB * HHh * SSq + row];
    float m = fmaxf(m0, m1);
    float c0 = __expf(m0 - m), c1 = __expf(m1 - m);
    float inv = 1.f / (c0 * s0v + c1 * s1v);
    float4 a = ((const float4*)o0)[i];
    float4 bb = ((const float4*)o1)[i];
    uint4 u;
    u.x = f2tf32((c0 * a.x + c1 * bb.x) * inv);
    u.y = f2tf32((c0 * a.y + c1 * bb.y) * inv);
    u.z = f2tf32((c0 * a.z + c1 * bb.z) * inv);
    u.w = f2tf32((c0 * a.w + c1 * bb.w) * inv);
    ((uint4*)attn)[i] = u;
}

// ---------------- residual + LayerNorm over (x0 + x1 + res), dual output ----------------
__global__ void ln_kernel2(const float* __restrict__ x0, const float* __restrict__ x1,
                           const float* __restrict__ res,
                           const float* __restrict__ g, const float* __restrict__ b,
                           float* __restrict__ out, float* __restrict__ outc)
{
    int row = blockIdx.x;
    const float* xr0 = x0 + (size_t)row * DDd;
    const float* xr1 = x1 + (size_t)row * DDd;
    const float* rr  = res + (size_t)row * DDd;
    __shared__ float redA[33], redB[33];
    int tid = threadIdx.x;

    float loc[4];
    float s1 = 0.f, s2 = 0.f;
#pragma unroll
    for (int i = 0; i < 4; i++) {
        int d = tid + i * 256;
        float v = xr0[d] + xr1[d] + rr[d];
        loc[i] = v;
        s1 += v;
        s2 += v * v;
    }
#pragma unroll
    for (int o = 16; o; o >>= 1) {
        s1 += __shfl_xor_sync(0xffffffffu, s1, o);
        s2 += __shfl_xor_sync(0xffffffffu, s2, o);
    }
    if ((tid & 31) == 0) { redA[tid >> 5] = s1; redB[tid >> 5] = s2; }
    __syncthreads();
    if (tid < 32) {
        float a = (tid < 8) ? redA[tid] : 0.f;
        float c = (tid < 8) ? redB[tid] : 0.f;
#pragma unroll
        for (int o = 4; o; o >>= 1) {
            a += __shfl_xor_sync(0xffffffffu, a, o);
            c += __shfl_xor_sync(0xffffffffu, c, o);
        }
        if (tid == 0) { redA[32] = a; redB[32] = c; }
    }
    __syncthreads();
    float mu  = redA[32] * (1.f / DDd);
    float var = redB[32] * (1.f / DDd) - mu * mu;
    float rstd = rsqrtf(var + 1e-5f);
#pragma unroll
    for (int i = 0; i < 4; i++) {
        int d = tid + i * 256;
        float o = (loc[i] - mu) * rstd * g[d] + b[d];
        out[(size_t)row * DDd + d] = o;
        if (outc) outc[(size_t)row * DDd + d] = __uint_as_float(f2tf32(o));
    }
}

// ---------------- host-side orchestration ----------------
extern "C" void kernel_launch(void* const* d_in, const int* in_sizes, int n_in,
                              void* d_out, int out_size)
{
    const float* x      = (const float*)d_in[0];
    const float* memory = (const float*)d_in[1];
    const float* Wq  = (const float*)d_in[2];
    const float* Wk  = (const float*)d_in[3];
    const float* Wv  = (const float*)d_in[4];
    const float* Wr  = (const float*)d_in[5];
    const float* Wo  = (const float*)d_in[6];
    const float* rwb = (const float*)d_in[7];
    const float* rrb = (const float*)d_in[8];
    const float* ln1g = (const float*)d_in[9];
    const float* ln1b = (const float*)d_in[10];
    const float* ln2g = (const float*)d_in[11];
    const float* ln2b = (const float*)d_in[12];
    const float* W1  = (const float*)d_in[13];
    const float* b1  = (const float*)d_in[14];
    const float* W2  = (const float*)d_in[15];
    const float* b2  = (const float*)d_in[16];
    float* out = (float*)d_out;

    float *pos, *q, *k, *v, *r, *attn, *tmp, *tmp2, *pm, *ps, *ff, *h, *hc, *h1, *h1c;
    float *wqc, *wkc, *wvc, *wrc, *woc, *w1c, *w2c, *memc, *xc;
    cudaGetSymbolAddress((void**)&pos,  g_pos);
    cudaGetSymbolAddress((void**)&q,    g_q);
    cudaGetSymbolAddress((void**)&k,    g_k);
    cudaGetSymbolAddress((void**)&v,    g_v);
    cudaGetSymbolAddress((void**)&r,    g_r);
    cudaGetSymbolAddress((void**)&attn, g_attn);
    cudaGetSymbolAddress((void**)&tmp,  g_tmp);
    cudaGetSymbolAddress((void**)&tmp2, g_tmp2);
    cudaGetSymbolAddress((void**)&pm,   g_pm);
    cudaGetSymbolAddress((void**)&ps,   g_ps);
    cudaGetSymbolAddress((void**)&ff,   g_ff);
    cudaGetSymbolAddress((void**)&h,    g_h);
    cudaGetSymbolAddress((void**)&hc,   g_hc);
    cudaGetSymbolAddress((void**)&h1,   g_h1);
    cudaGetSymbolAddress((void**)&h1c,  g_h1c);
    cudaGetSymbolAddress((void**)&wqc,  g_wqc);
    cudaGetSymbolAddress((void**)&wkc,  g_wkc);
    cudaGetSymbolAddress((void**)&wvc,  g_wvc);
    cudaGetSymbolAddress((void**)&wrc,  g_wrc);
    cudaGetSymbolAddress((void**)&woc,  g_woc);
    cudaGetSymbolAddress((void**)&w1c,  g_w1c);
    cudaGetSymbolAddress((void**)&w2c,  g_w2c);
    cudaGetSymbolAddress((void**)&memc, g_memc);
    cudaGetSymbolAddress((void**)&xc,   g_xc);

    cudaFuncSetAttribute(fused_attn_split, cudaFuncAttributeMaxDynamicSharedMemorySize,
                         SMEM_ATTN_BYTES);

    auto cvt = [&](const float* in, float* o, size_t n) {
        int n4 = (int)(n / 4);
        cvt_tf32_kernel<<<(n4 + 255) / 256, 256>>>(in, o, n4);
    };
    cvt(Wq, wqc, (size_t)LL * DDd * DDd);
    cvt(Wk, wkc, (size_t)LL * DDd * DDd);
    cvt(Wv, wvc, (size_t)LL * DDd * DDd);
    cvt(Wr, wrc, (size_t)LL * DDd * DDd);
    cvt(Wo, woc, (size_t)LL * DDd * DDd);
    cvt(W1, w1c, (size_t)LL * DDd * FFf);
    cvt(W2, w2c, (size_t)LL * FFf * DDd);
    cvt(memory, memc, (size_t)LL * BB * MMm * DDd);
    cvt(x, xc, (size_t)BB * SSq * DDd);

    pos_kernel<<<(TTt * (DDd / 2) + 255) / 256, 256>>>(pos);

    const float* hcur  = x;
    const float* hcurc = xc;
    for (int l = 0; l < LL; l++) {
        dim3 gG(DDd / 128, 48);
        grouped_qkvr<<<gG, 256>>>(hcurc, memc + (size_t)l * BB * MMm * DDd, pos,
                                  wqc + (size_t)l * DDd * DDd, wkc + (size_t)l * DDd * DDd,
                                  wvc + (size_t)l * DDd * DDd, wrc + (size_t)l * DDd * DDd,
                                  q, k, v, r);

        // split-T flash attention: 1024 CTAs, partials into tmp/tmp2
        dim3 gA(SSq / SMT, BB * HHh, 2);
        fused_attn_split<<<gA, 256, SMEM_ATTN_BYTES>>>(
            q, k, v, r, rwb + (size_t)l * HHh * DKk, rrb + (size_t)l * HHh * DKk,
            tmp, tmp2, pm, ps);
        attn_combine<<<(BB * SSq * DDd / 4 + 255) / 256, 256>>>(tmp, tmp2, pm, ps, attn);

        dim3 gO(DDd / 128, (BB * SSq) / 64, 2);
        tc_gemm_splitk<64, 4><<<gO, 256>>>(attn, woc + (size_t)l * DDd * DDd,
                                           tmp, tmp2, DDd, DDd, nullptr);
        ln_kernel2<<<BB * SSq, 256>>>(tmp, tmp2, hcur,
                                      ln1g + l * DDd, ln1b + l * DDd, h1, h1c);

        dim3 gF1(FFf / 128, (BB * SSq) / 128);
        tc_gemm_k<128, 4><<<gF1, 256>>>(h1c, w1c + (size_t)l * DDd * FFf, ff,
                                        FFf, DDd, 1.f, b1 + l * FFf, 1, 1);
        dim3 gF2(DDd / 128, (BB * SSq) / 64, 2);
        tc_gemm_splitk<64, 4><<<gF2, 256>>>(ff, w2c + (size_t)l * FFf * DDd,
                                            tmp, tmp2, DDd, FFf, b2 + l * DDd);

        if (l == LL - 1) {
            ln_kernel2<<<BB * SSq, 256>>>(tmp, tmp2, h1,
                                          ln2g + l * DDd, ln2b + l * DDd, out, nullptr);
        } else {
            ln_kernel2<<<BB * SSq, 256>>>(tmp, tmp2, h1,
                                          ln2g + l * DDd, ln2b + l * DDd, h, hc);
            hcur = h;
            hcurc = hc;
        }
    }
}

// round 13
// speedup vs baseline: 1.0408x; 1.0156x over previous
#include <cuda_runtime.h>
#include <math.h>
#include <stdint.h>

// Problem dims
#define LL  4
#define BB  2
#define SSq 512
#define MMm 512
#define DDd 1024
#define HHh 16
#define DKk 64
#define FFf 4096
#define TTt (SSq + MMm)   // 1024
#define NZ  4             // attention T-split factor

// ---------------- scratch ----------------
__device__ float g_pos[TTt * DDd];        // tf32 bits
__device__ float g_q  [BB * SSq * DDd];   // fp32
__device__ float g_k  [BB * TTt * DDd];   // tf32 bits
__device__ float g_v  [BB * TTt * DDd];   // tf32 bits
__device__ float g_r  [TTt * DDd];        // tf32 bits
__device__ float g_attn[BB * SSq * DDd];  // tf32 bits
__device__ float g_tmp [BB * SSq * DDd];  // O-partial z=0 / o-proj partial
__device__ float g_tmp2[BB * SSq * DDd];  // O-partial z=1 / o-proj partial
__device__ float g_tmp3[BB * SSq * DDd];  // O-partial z=2
__device__ float g_tmp4[BB * SSq * DDd];  // O-partial z=3
__device__ float g_pm [NZ * BB * HHh * SSq];
__device__ float g_ps [NZ * BB * HHh * SSq];
__device__ float g_ff  [BB * SSq * FFf];  // tf32 bits
__device__ float g_h   [BB * SSq * DDd];  // fp32 residual
__device__ float g_hc  [BB * SSq * DDd];  // tf32 copy
__device__ float g_h1  [BB * SSq * DDd];  // fp32 residual
__device__ float g_h1c [BB * SSq * DDd];  // tf32 copy
// pre-converted operands (tf32 bits)
__device__ float g_wqc[LL * DDd * DDd];
__device__ float g_wkc[LL * DDd * DDd];
__device__ float g_wvc[LL * DDd * DDd];
__device__ float g_wrc[LL * DDd * DDd];
__device__ float g_woc[LL * DDd * DDd];
__device__ float g_w1c[LL * DDd * FFf];
__device__ float g_w2c[LL * FFf * DDd];
__device__ float g_memc[LL * BB * MMm * DDd];
__device__ float g_xc  [BB * SSq * DDd];

// ---------------- PTX helpers ----------------
__device__ __forceinline__ uint32_t f2tf32(float f) {
    uint32_t u;
    asm("cvt.rna.tf32.f32 %0, %1;" : "=r"(u) : "f"(f));
    return u;
}
__device__ __forceinline__ void mma_tf32(float c[4], const uint32_t a[4], const uint32_t b[2]) {
    asm volatile(
        "mma.sync.aligned.m16n8k8.row.col.f32.tf32.tf32.f32 "
        "{%0,%1,%2,%3},{%4,%5,%6,%7},{%8,%9},{%0,%1,%2,%3};"
        : "+f"(c[0]), "+f"(c[1]), "+f"(c[2]), "+f"(c[3])
        : "r"(a[0]), "r"(a[1]), "r"(a[2]), "r"(a[3]), "r"(b[0]), "r"(b[1]));
}
__device__ __forceinline__ void cp_async16(void* smem, const void* g) {
    uint32_t s = (uint32_t)__cvta_generic_to_shared(smem);
    asm volatile("cp.async.cg.shared.global [%0], [%1], 16;" :: "r"(s), "l"(g));
}
#define CP_COMMIT() asm volatile("cp.async.commit_group;")
#define CP_WAIT(n)  asm volatile("cp.async.wait_group %0;" :: "n"(n))

__device__ __forceinline__ uint32_t sm_u32(const void* p) {
    return (uint32_t)__cvta_generic_to_shared(p);
}
__device__ __forceinline__ void ldsm_x4(uint32_t r[4], uint32_t addr) {
    asm volatile("ldmatrix.sync.aligned.m8n8.x4.shared.b16 {%0,%1,%2,%3}, [%4];"
                 : "=r"(r[0]), "=r"(r[1]), "=r"(r[2]), "=r"(r[3]) : "r"(addr));
}
__device__ __forceinline__ void ldsm_x2(uint32_t r[2], uint32_t addr) {
    asm volatile("ldmatrix.sync.aligned.m8n8.x2.shared.b16 {%0,%1}, [%2];"
                 : "=r"(r[0]), "=r"(r[1]) : "r"(addr));
}

// ---------------- flattened 9-region fp32 -> tf32-bit convert ----------------
struct CvtP {
    const float* in[9];
    float* out[9];
    int cum[10];   // cumulative block counts (each block = 256 float4)
};
__global__ void cvt_all9(CvtP p)
{
    int blk = blockIdx.x;
    int r = 0;
#pragma unroll
    for (int j = 1; j < 9; j++) r += (blk >= p.cum[j]);
    int i = (blk - p.cum[r]) * 256 + threadIdx.x;
    float4 v = ((const float4*)p.in[r])[i];
    uint4 u = make_uint4(f2tf32(v.x), f2tf32(v.y), f2tf32(v.z), f2tf32(v.w));
    ((uint4*)p.out[r])[i] = u;
}

// ---------------- positional encodings (tf32 out) ----------------
__global__ void pos_kernel(float* __restrict__ pos)
{
    int idx = blockIdx.x * blockDim.x + threadIdx.x;
    if (idx >= TTt * (DDd / 2)) return;
    int t = idx / (DDd / 2), j = idx % (DDd / 2);
    double invf = exp(((double)(-2 * j) / (double)DDd) * 9.210340371976184);
    double ang  = (double)(TTt - 1 - t) * invf;
    double kk   = floor(ang * 0.15915494309189535);
    float a = (float)(ang - kk * 6.283185307179586);
    pos[(size_t)t * DDd + j]           = __uint_as_float(f2tf32(sinf(a)));
    pos[(size_t)t * DDd + j + DDd / 2] = __uint_as_float(f2tf32(cosf(a)));
}

// ======================================================================
// Async GEMM core (R9 verified): pre-converted tf32 operands.
// ======================================================================
template<int BM, int NWN>
__device__ __forceinline__ void gemm_core_async(
    const float* __restrict__ Ag, const float* __restrict__ Bg, float* __restrict__ Cg,
    int N, int K, int lda, float alpha, const float* __restrict__ biasg, int relu,
    int cvt_out)
{
    constexpr int BN = NWN * 32;
    constexpr int NWM = 8 / NWN;
    constexpr int WM = BM / NWM;
    constexpr int MT = WM / 16;
    constexpr int BPITCH = BN + 8;
    constexpr int NA_CH = BM / 64;
    constexpr int NB_CH = BN / 64;

    __shared__ uint32_t As[2][BM][20];
    __shared__ uint32_t Bs[2][16][BPITCH];

    int tid = threadIdx.x, lane = tid & 31, warp = tid >> 5;
    int g = lane >> 2, tg = lane & 3;
    int warp_m = warp % NWM, warp_n = warp / NWM;
    int wm = warp_m * WM, wn = warp_n * 32;

    float acc[MT][4][4];
#pragma unroll
    for (int mt = 0; mt < MT; mt++)
#pragma unroll
        for (int nt = 0; nt < 4; nt++)
#pragma unroll
            for (int i = 0; i < 4; i++) acc[mt][nt][i] = 0.f;

    int ar[NA_CH], ak[NA_CH];
#pragma unroll
    for (int j = 0; j < NA_CH; j++) {
        int c = tid + j * 256;
        ar[j] = c >> 2; ak[j] = (c & 3) * 4;
    }
    int bk[NB_CH], bn[NB_CH];
#pragma unroll
    for (int j = 0; j < NB_CH; j++) {
        int c = tid + j * 256;
        if (BN == 128) { bk[j] = c >> 5; bn[j] = (c & 31) * 4; }
        else           { bk[j] = c >> 4; bn[j] = (c & 15) * 4; }
    }

    int nk = K / 16;

#pragma unroll
    for (int j = 0; j < NA_CH; j++)
        cp_async16(&As[0][ar[j]][ak[j]], Ag + (size_t)ar[j] * lda + ak[j]);
#pragma unroll
    for (int j = 0; j < NB_CH; j++)
        cp_async16(&Bs[0][bk[j]][bn[j]], Bg + (size_t)bk[j] * N + bn[j]);
    CP_COMMIT();

    for (int kt = 0; kt < nk; kt++) {
        int buf = kt & 1;
        bool more = (kt + 1 < nk);
        if (more) {
            int nb = buf ^ 1;
#pragma unroll
            for (int j = 0; j < NA_CH; j++)
                cp_async16(&As[nb][ar[j]][ak[j]],
                           Ag + (size_t)ar[j] * lda + (kt + 1) * 16 + ak[j]);
#pragma unroll
            for (int j = 0; j < NB_CH; j++)
                cp_async16(&Bs[nb][bk[j]][bn[j]],
                           Bg + (size_t)((kt + 1) * 16 + bk[j]) * N + bn[j]);
            CP_COMMIT();
            CP_WAIT(1);
        } else {
            CP_WAIT(0);
        }
        __syncthreads();

#pragma unroll
        for (int ks = 0; ks < 2; ks++) {
            uint32_t af[MT][4], bf[4][2];
#pragma unroll
            for (int mt = 0; mt < MT; mt++) {
                int row = wm + mt * 16;
                af[mt][0] = As[buf][row + g][ks * 8 + tg];
                af[mt][1] = As[buf][row + g + 8][ks * 8 + tg];
                af[mt][2] = As[buf][row + g][ks * 8 + tg + 4];
                af[mt][3] = As[buf][row + g + 8][ks * 8 + tg + 4];
            }
#pragma unroll
            for (int nt = 0; nt < 4; nt++) {
                int col = wn + nt * 8 + g;
                bf[nt][0] = Bs[buf][ks * 8 + tg][col];
                bf[nt][1] = Bs[buf][ks * 8 + tg + 4][col];
            }
#pragma unroll
            for (int mt = 0; mt < MT; mt++)
#pragma unroll
                for (int nt = 0; nt < 4; nt++) mma_tf32(acc[mt][nt], af[mt], bf[nt]);
        }
        if (more) __syncthreads();
    }

#pragma unroll
    for (int mt = 0; mt < MT; mt++) {
#pragma unroll
        for (int nt = 0; nt < 4; nt++) {
            int row = wm + mt * 16 + g;
            int col = wn + nt * 8 + tg * 2;
            float bx0 = 0.f, bx1 = 0.f;
            if (biasg) { bx0 = biasg[col]; bx1 = biasg[col + 1]; }
            float v0 = acc[mt][nt][0] * alpha + bx0;
            float v1 = acc[mt][nt][1] * alpha + bx1;
            float v2 = acc[mt][nt][2] * alpha + bx0;
            float v3 = acc[mt][nt][3] * alpha + bx1;
            if (relu) {
                v0 = fmaxf(v0, 0.f); v1 = fmaxf(v1, 0.f);
                v2 = fmaxf(v2, 0.f); v3 = fmaxf(v3, 0.f);
            }
            if (cvt_out) {
                v0 = __uint_as_float(f2tf32(v0));
                v1 = __uint_as_float(f2tf32(v1));
                v2 = __uint_as_float(f2tf32(v2));
                v3 = __uint_as_float(f2tf32(v3));
            }
            *(float2*)(Cg + (size_t)row * N + col)       = make_float2(v0, v1);
            *(float2*)(Cg + (size_t)(row + 8) * N + col) = make_float2(v2, v3);
        }
    }
}

template<int BM, int NWN>
__global__ void __launch_bounds__(256) tc_gemm_k(
    const float* __restrict__ A, const float* __restrict__ B, float* __restrict__ C,
    int N, int K, float alpha, const float* __restrict__ bias, int relu, int cvt_out)
{
    constexpr int BN = NWN * 32;
    const float* Ag = A + (size_t)blockIdx.y * BM * K;
    const float* Bg = B + (size_t)blockIdx.x * BN;
    float* Cg = C + (size_t)blockIdx.y * BM * N + (size_t)blockIdx.x * BN;
    const float* bg = bias ? bias + (size_t)blockIdx.x * BN : nullptr;
    gemm_core_async<BM, NWN>(Ag, Bg, Cg, N, K, K, alpha, bg, relu, cvt_out);
}

template<int BM, int NWN>
__global__ void __launch_bounds__(256) tc_gemm_splitk(
    const float* __restrict__ A, const float* __restrict__ B,
    float* __restrict__ C0, float* __restrict__ C1,
    int N, int K, const float* __restrict__ bias)
{
    constexpr int BN = NWN * 32;
    int z = blockIdx.z;
    int K2 = K >> 1;
    const float* Ag = A + (size_t)blockIdx.y * BM * K + (size_t)z * K2;
    const float* Bg = B + (size_t)z * K2 * N + (size_t)blockIdx.x * BN;
    float* C = z ? C1 : C0;
    float* Cg = C + (size_t)blockIdx.y * BM * N + (size_t)blockIdx.x * BN;
    const float* bg = (bias && z == 0) ? bias + (size_t)blockIdx.x * BN : nullptr;
    gemm_core_async<BM, NWN>(Ag, Bg, Cg, N, K2, K, 1.f, bg, 0, 0);
}

// grouped q/k/v/r projections (R9 verified)
__global__ void __launch_bounds__(256) grouped_qkvr(
    const float* __restrict__ hcc, const float* __restrict__ memc, const float* __restrict__ pos,
    const float* __restrict__ Wq, const float* __restrict__ Wk,
    const float* __restrict__ Wv, const float* __restrict__ Wr,
    float* __restrict__ q, float* __restrict__ k, float* __restrict__ v, float* __restrict__ r)
{
    int y = blockIdx.y;
    const float* Ag; const float* B; float* C; float alpha = 1.f; int cvt = 1;
    if (y < 8) {
        Ag = hcc + (size_t)y * 128 * DDd; B = Wq; C = q + (size_t)y * 128 * DDd;
        alpha = 0.125f; cvt = 0;
    } else if (y < 40) {
        int yy = (y < 24) ? y - 8 : y - 24;
        int row0 = yy * 128;
        int b = row0 >> 10, t0 = row0 & 1023;
        Ag = (t0 < MMm) ? memc + ((size_t)b * MMm + t0) * DDd
                        : hcc  + ((size_t)b * SSq + (t0 - MMm)) * DDd;
        if (y < 24) { B = Wk; C = k + (size_t)yy * 128 * DDd; }
        else        { B = Wv; C = v + (size_t)yy * 128 * DDd; }
    } else {
        int yy = y - 40;
        Ag = pos + (size_t)yy * 128 * DDd; B = Wr; C = r + (size_t)yy * 128 * DDd;
    }
    const float* Bg = B + (size_t)blockIdx.x * 128;
    float* Cg = C + (size_t)blockIdx.x * 128;
    gemm_core_async<128, 4>(Ag, Bg, Cg, DDd, DDd, DDd, alpha, nullptr, 0, cvt);
}

// ======================================================================
// Flash fused attention, split over T into NZ partitions.
// Writes UNNORMALIZED O partial + per-row (m, sum) stats.
// ======================================================================
#define SMT   32
#define TN    64
#define QPITCH 68
#define WPITCH 100
#define SMEM_ATTN_FLOATS (2*SMT*QPITCH + 64*QPITCH + 96*QPITCH + 64*QPITCH + SMT*QPITCH + SMT*WPITCH + 96)
#define SMEM_ATTN_BYTES  (SMEM_ATTN_FLOATS * 4)

__global__ void __launch_bounds__(256) fused_attn_split(
    const float* __restrict__ q, const float* __restrict__ k, const float* __restrict__ v,
    const float* __restrict__ r, const float* __restrict__ rwb, const float* __restrict__ rrb,
    float* __restrict__ o0, float* __restrict__ o1,
    float* __restrict__ o2, float* __restrict__ o3,
    float* __restrict__ pm, float* __restrict__ ps)
{
    extern __shared__ float sm[];
    uint32_t* Qcb  = (uint32_t*)sm;
    uint32_t* Qrb  = Qcb + SMT * QPITCH;
    uint32_t* Ktb  = Qrb + SMT * QPITCH;
    uint32_t* Rwb  = Ktb + 64 * QPITCH;
    uint32_t* Vtb  = Rwb + 96 * QPITCH;
    float*    Lt   = (float*)(Vtb + 64 * QPITCH);
    float*    QRW  = Lt + SMT * QPITCH;
    float*    crow = QRW + SMT * WPITCH;
    float*    rowm = crow + 32;
    float*    rowsum = rowm + 32;
    uint32_t* Ltb  = (uint32_t*)Lt;

    int tid = threadIdx.x, lane = tid & 31, warp = tid >> 5;
    int g = lane >> 2, tg = lane & 3;
    int s0 = (15 - blockIdx.x) * SMT;
    int b = blockIdx.y >> 4, h = blockIdx.y & 15;
    int z = blockIdx.z;

    const float* qb = q + (size_t)b * SSq * DDd + h * DKk;
    const float* kb = k + (size_t)b * TTt * DDd + h * DKk;
    const float* vb = v + (size_t)b * TTt * DDd + h * DKk;
    const float* rb = r + h * DKk;
    const float* wbv = rwb + h * DKk;
    const float* rbv = rrb + h * DKk;

    int ntiles = (s0 + 543) / 64 + 1;
    int tbeg = (z * ntiles) / NZ;
    int tend = ((z + 1) * ntiles) / NZ;

    int lrow = tid >> 4, lk0 = (tid & 15) * 4;

    auto issue_KR = [&](int it) {
        if (it < tend) {
            int t0 = it * TN, jb = t0 - s0 + 480;
#pragma unroll
            for (int j = 0; j < 4; j++) {
                int row = lrow + j * 16;
                cp_async16(&Ktb[row * QPITCH + lk0], kb + (size_t)(t0 + row) * DDd + lk0);
            }
#pragma unroll
            for (int j = 0; j < 6; j++) {
                int row = lrow + j * 16;
                int jg = jb + row;
                if (jg > TTt - 1) jg = TTt - 1;
                if (jg < 0) jg = 0;
                cp_async16(&Rwb[row * QPITCH + lk0], rb + (size_t)jg * DDd + lk0);
            }
        }
        CP_COMMIT();
    };
    auto issue_V = [&](int it) {
        if (it < tend) {
            int t0 = it * TN;
#pragma unroll
            for (int j = 0; j < 4; j++) {
                int row = lrow + j * 16;
                cp_async16(&Vtb[row * QPITCH + lk0], vb + (size_t)(t0 + row) * DDd + lk0);
            }
        }
        CP_COMMIT();
    };

    issue_KR(tbeg);

#pragma unroll
    for (int j = 0; j < 2; j++) {
        int c = tid + j * 256;
        int row = c >> 4, k0 = (c & 15) * 4;
        float4 qv = *(const float4*)(qb + (size_t)(s0 + row) * DDd + k0);
        float4 w4 = *(const float4*)(wbv + k0);
        float4 r4 = *(const float4*)(rbv + k0);
        Qcb[row * QPITCH + k0 + 0] = f2tf32(qv.x + w4.x);
        Qcb[row * QPITCH + k0 + 1] = f2tf32(qv.y + w4.y);
        Qcb[row * QPITCH + k0 + 2] = f2tf32(qv.z + w4.z);
        Qcb[row * QPITCH + k0 + 3] = f2tf32(qv.w + w4.w);
        Qrb[row * QPITCH + k0 + 0] = f2tf32(qv.x + r4.x);
        Qrb[row * QPITCH + k0 + 1] = f2tf32(qv.y + r4.y);
        Qrb[row * QPITCH + k0 + 2] = f2tf32(qv.z + r4.z);
        Qrb[row * QPITCH + k0 + 3] = f2tf32(qv.w + r4.w);
    }
    if (tid < 32) { rowm[tid] = -1e30f; rowsum[tid] = 0.f; }

    int wm2 = (warp & 1) * 16;
    int wn2 = (warp >> 1) * 16;
    int wn3 = (warp >> 1) * 24;
    int r1 = wm2 + g, r2 = r1 + 8;

    int srow = warp * 4 + (lane >> 3);
    int scol = (lane & 7) * 8;

    int a_row = (lane & 7) + ((lane >> 3) & 1) * 8;
    int a_col = (lane >> 4) * 4;
    int b_row = (lane & 7) + ((lane >> 4) & 1) * 8;
    int b_col = ((lane >> 3) & 1) * 4;
    int c_row = lane & 7;
    int c_col = ((lane >> 3) & 1) * 4;

    uint32_t qc_a  = sm_u32(&Qcb[(wm2 + a_row) * QPITCH + a_col]);
    uint32_t qr_a  = sm_u32(&Qrb[(wm2 + a_row) * QPITCH + a_col]);
    uint32_t lt_a  = sm_u32(&Ltb[(wm2 + a_row) * QPITCH + a_col]);
    uint32_t kt_a  = sm_u32(&Ktb[(wn2 + b_row) * QPITCH + b_col]);
    uint32_t rw4_a = sm_u32(&Rwb[(wn3 + b_row) * QPITCH + b_col]);
    uint32_t rw2_a = sm_u32(&Rwb[(wn3 + 16 + c_row) * QPITCH + c_col]);

    float oacc[2][4];
#pragma unroll
    for (int nt = 0; nt < 2; nt++)
#pragma unroll
        for (int i = 0; i < 4; i++) oacc[nt][i] = 0.f;

    for (int it = tbeg; it < tend; it++) {
        int t0 = it * TN;
        CP_WAIT(0);
        __syncthreads();     // sync A

        issue_V(it);

        float ca[2][4], ra[3][4];
#pragma unroll
        for (int nt = 0; nt < 2; nt++)
#pragma unroll
            for (int i = 0; i < 4; i++) ca[nt][i] = 0.f;
#pragma unroll
        for (int nt = 0; nt < 3; nt++)
#pragma unroll
            for (int i = 0; i < 4; i++) ra[nt][i] = 0.f;

#pragma unroll
        for (int k8 = 0; k8 < 64; k8 += 8) {
            uint32_t koff = k8 * 4;
            uint32_t af[4], afr[4], bk4[4], br4[4], br2[2];
            ldsm_x4(af,  qc_a + koff);
            ldsm_x4(afr, qr_a + koff);
            ldsm_x4(bk4, kt_a + koff);
            ldsm_x4(br4, rw4_a + koff);
            ldsm_x2(br2, rw2_a + koff);
            {
                uint32_t bf0[2] = {bk4[0], bk4[1]};
                uint32_t bf1[2] = {bk4[2], bk4[3]};
                mma_tf32(ca[0], af, bf0);
                mma_tf32(ca[1], af, bf1);
            }
            {
                uint32_t bf0[2] = {br4[0], br4[1]};
                uint32_t bf1[2] = {br4[2], br4[3]};
                mma_tf32(ra[0], afr, bf0);
                mma_tf32(ra[1], afr, bf1);
                mma_tf32(ra[2], afr, br2);
            }
        }
#pragma unroll
        for (int nt = 0; nt < 2; nt++) {
            int c0 = wn2 + nt * 8 + tg * 2;
            Lt[r1 * QPITCH + c0]     = ca[nt][0];
            Lt[r1 * QPITCH + c0 + 1] = ca[nt][1];
            Lt[r2 * QPITCH + c0]     = ca[nt][2];
            Lt[r2 * QPITCH + c0 + 1] = ca[nt][3];
        }
#pragma unroll
        for (int nt = 0; nt < 3; nt++) {
            int c0 = wn3 + nt * 8 + tg * 2;
            QRW[r1 * WPITCH + c0]     = ra[nt][0];
            QRW[r1 * WPITCH + c0 + 1] = ra[nt][1];
            QRW[r2 * WPITCH + c0]     = ra[nt][2];
            QRW[r2 * WPITCH + c0 + 1] = ra[nt][3];
        }
        __syncthreads();     // sync B

        issue_KR(it + 1);

        // warp-exclusive row softmax
        {
            float4 ca4 = *(const float4*)&Lt[srow * QPITCH + scol];
            float4 cb4 = *(const float4*)&Lt[srow * QPITCH + scol + 4];
            float lv[8] = {ca4.x, ca4.y, ca4.z, ca4.w, cb4.x, cb4.y, cb4.z, cb4.w};
            const float* qr = &QRW[srow * WPITCH + scol + 31 - srow];
            int lim = MMm - t0 + s0 + srow;
#pragma unroll
            for (int j = 0; j < 8; j++) {
                float lvv = lv[j] + qr[j];
                lv[j] = (scol + j <= lim) ? lvv : -1e30f;
            }
            float tmax = lv[0];
#pragma unroll
            for (int j = 1; j < 8; j++) tmax = fmaxf(tmax, lv[j]);
            tmax = fmaxf(tmax, __shfl_xor_sync(0xffffffffu, tmax, 1));
            tmax = fmaxf(tmax, __shfl_xor_sync(0xffffffffu, tmax, 2));
            tmax = fmaxf(tmax, __shfl_xor_sync(0xffffffffu, tmax, 4));
            float m_old = rowm[srow];
            float m_new = fmaxf(m_old, tmax);
            float cfac = __expf(m_old - m_new);
            float p[8], tsum = 0.f;
#pragma unroll
            for (int j = 0; j < 8; j++) {
                p[j] = __expf(lv[j] - m_new);
                tsum += p[j];
            }
            tsum += __shfl_xor_sync(0xffffffffu, tsum, 1);
            tsum += __shfl_xor_sync(0xffffffffu, tsum, 2);
            tsum += __shfl_xor_sync(0xffffffffu, tsum, 4);
            uint4 u0 = make_uint4(f2tf32(p[0]), f2tf32(p[1]), f2tf32(p[2]), f2tf32(p[3]));
            uint4 u1 = make_uint4(f2tf32(p[4]), f2tf32(p[5]), f2tf32(p[6]), f2tf32(p[7]));
            *(uint4*)&Ltb[srow * QPITCH + scol]     = u0;
            *(uint4*)&Ltb[srow * QPITCH + scol + 4] = u1;
            if ((lane & 7) == 0) {
                rowm[srow] = m_new;
                rowsum[srow] = rowsum[srow] * cfac + tsum;
                crow[srow] = cfac;
            }
        }

        CP_WAIT(1);
        __syncthreads();     // sync C

        float c1 = crow[r1], c2 = crow[r2];
#pragma unroll
        for (int nt = 0; nt < 2; nt++) {
            oacc[nt][0] *= c1; oacc[nt][1] *= c1;
            oacc[nt][2] *= c2; oacc[nt][3] *= c2;
        }
#pragma unroll
        for (int k8 = 0; k8 < 64; k8 += 8) {
            uint32_t af[4];
            ldsm_x4(af, lt_a + k8 * 4);
#pragma unroll
            for (int nt = 0; nt < 2; nt++) {
                uint32_t bf[2];
                int col = wn2 + nt * 8 + g;
                bf[0] = Vtb[(k8 + tg) * QPITCH + col];
                bf[1] = Vtb[(k8 + tg + 4) * QPITCH + col];
                mma_tf32(oacc[nt], af, bf);
            }
        }
    }

    __syncthreads();
    float* ozb = (z == 0) ? o0 : (z == 1) ? o1 : (z == 2) ? o2 : o3;
    float* oz = ozb + ((size_t)b * SSq + s0) * DDd + h * DKk;
#pragma unroll
    for (int nt = 0; nt < 2; nt++) {
        int c0 = wn2 + nt * 8 + tg * 2;
        *(float2*)(oz + (size_t)r1 * DDd + c0) = make_float2(oacc[nt][0], oacc[nt][1]);
        *(float2*)(oz + (size_t)r2 * DDd + c0) = make_float2(oacc[nt][2], oacc[nt][3]);
    }
    if (warp < 2 && tg == 0) {
        int zoff = z * (BB * HHh * SSq);
        int base = blockIdx.y * SSq + s0;
        pm[zoff + base + r1] = rowm[r1];
        ps[zoff + base + r1] = rowsum[r1];
        pm[zoff + base + r2] = rowm[r2];
        ps[zoff + base + r2] = rowsum[r2];
    }
}

// ---------------- combine NZ split-attention partials -> attn (tf32 bits) ---
__global__ void attn_combine(const float* __restrict__ o0, const float* __restrict__ o1,
                             const float* __restrict__ o2, const float* __restrict__ o3,
                             const float* __restrict__ pm, const float* __restrict__ ps,
                             float* __restrict__ attn)
{
    int i = blockIdx.x * 256 + threadIdx.x;     // float4 index
    if (i >= (BB * SSq * DDd) / 4) return;
    int e = i * 4;
    int d = e & (DDd - 1);
    int h = d >> 6;
    int s = (e >> 10) & (SSq - 1);
    int b = e >> 19;
    int row = (b * HHh + h) * SSq + s;
    const int Z = BB * HHh * SSq;
    float m0 = pm[row], m1 = pm[Z + row], m2 = pm[2 * Z + row], m3 = pm[3 * Z + row];
    float s0v = ps[row], s1v = ps[Z + row], s2v = ps[2 * Z + row], s3v = ps[3 * Z + row];
    float m = fmaxf(fmaxf(m0, m1), fmaxf(m2, m3));
    float c0 = __expf(m0 - m), c1 = __expf(m1 - m);
    float c2 = __expf(m2 - m), c3 = __expf(m3 - m);
    float inv = 1.f / (c0 * s0v + c1 * s1v + c2 * s2v + c3 * s3v);
    float4 a0 = ((const float4*)o0)[i];
    float4 a1 = ((const float4*)o1)[i];
    float4 a2 = ((const float4*)o2)[i];
    float4 a3 = ((const float4*)o3)[i];
    uint4 u;
    u.x = f2tf32((c0 * a0.x + c1 * a1.x + c2 * a2.x + c3 * a3.x) * inv);
    u.y = f2tf32((c0 * a0.y + c1 * a1.y + c2 * a2.y + c3 * a3.y) * inv);
    u.z = f2tf32((c0 * a0.z + c1 * a1.z + c2 * a2.z + c3 * a3.z) * inv);
    u.w = f2tf32((c0 * a0.w + c1 * a1.w + c2 * a2.w + c3 * a3.w) * inv);
    ((uint4*)attn)[i] = u;
}

// ---------------- residual + LayerNorm over (x0 + x1 + res), dual output ----------------
__global__ void ln_kernel2(const float* __restrict__ x0, const float* __restrict__ x1,
                           const float* __restrict__ res,
                           const float* __restrict__ g, const float* __restrict__ b,
                           float* __restrict__ out, float* __restrict__ outc)
{
    int row = blockIdx.x;
    const float* xr0 = x0 + (size_t)row * DDd;
    const float* xr1 = x1 + (size_t)row * DDd;
    const float* rr  = res + (size_t)row * DDd;
    __shared__ float redA[33], redB[33];
    int tid = threadIdx.x;

    float loc[4];
    float s1 = 0.f, s2 = 0.f;
#pragma unroll
    for (int i = 0; i < 4; i++) {
        int d = tid + i * 256;
        float v = xr0[d] + xr1[d] + rr[d];
        loc[i] = v;
        s1 += v;
        s2 += v * v;
    }
#pragma unroll
    for (int o = 16; o; o >>= 1) {
        s1 += __shfl_xor_sync(0xffffffffu, s1, o);
        s2 += __shfl_xor_sync(0xffffffffu, s2, o);
    }
    if ((tid & 31) == 0) { redA[tid >> 5] = s1; redB[tid >> 5] = s2; }
    __syncthreads();
    if (tid < 32) {
        float a = (tid < 8) ? redA[tid] : 0.f;
        float c = (tid < 8) ? redB[tid] : 0.f;
#pragma unroll
        for (int o = 4; o; o >>= 1) {
            a += __shfl_xor_sync(0xffffffffu, a, o);
            c += __shfl_xor_sync(0xffffffffu, c, o);
        }
        if (tid == 0) { redA[32] = a; redB[32] = c; }
    }
    __syncthreads();
    float mu  = redA[32] * (1.f / DDd);
    float var = redB[32] * (1.f / DDd) - mu * mu;
    float rstd = rsqrtf(var + 1e-5f);
#pragma unroll
    for (int i = 0; i < 4; i++) {
        int d = tid + i * 256;
        float o = (loc[i] - mu) * rstd * g[d] + b[d];
        out[(size_t)row * DDd + d] = o;
        if (outc) outc[(size_t)row * DDd + d] = __uint_as_float(f2tf32(o));
    }
}

// ---------------- host-side orchestration ----------------
extern "C" void kernel_launch(void* const* d_in, const int* in_sizes, int n_in,
                              void* d_out, int out_size)
{
    const float* x      = (const float*)d_in[0];
    const float* memory = (const float*)d_in[1];
    const float* Wq  = (const float*)d_in[2];
    const float* Wk  = (const float*)d_in[3];
    const float* Wv  = (const float*)d_in[4];
    const float* Wr  = (const float*)d_in[5];
    const float* Wo  = (const float*)d_in[6];
    const float* rwb = (const float*)d_in[7];
    const float* rrb = (const float*)d_in[8];
    const float* ln1g = (const float*)d_in[9];
    const float* ln1b = (const float*)d_in[10];
    const float* ln2g = (const float*)d_in[11];
    const float* ln2b = (const float*)d_in[12];
    const float* W1  = (const float*)d_in[13];
    const float* b1  = (const float*)d_in[14];
    const float* W2  = (const float*)d_in[15];
    const float* b2  = (const float*)d_in[16];
    float* out = (float*)d_out;

    float *pos, *q, *k, *v, *r, *attn, *tmp, *tmp2, *tmp3, *tmp4, *pm, *ps;
    float *ff, *h, *hc, *h1, *h1c;
    float *wqc, *wkc, *wvc, *wrc, *woc, *w1c, *w2c, *memc, *xc;
    cudaGetSymbolAddress((void**)&pos,  g_pos);
    cudaGetSymbolAddress((void**)&q,    g_q);
    cudaGetSymbolAddress((void**)&k,    g_k);
    cudaGetSymbolAddress((void**)&v,    g_v);
    cudaGetSymbolAddress((void**)&r,    g_r);
    cudaGetSymbolAddress((void**)&attn, g_attn);
    cudaGetSymbolAddress((void**)&tmp,  g_tmp);
    cudaGetSymbolAddress((void**)&tmp2, g_tmp2);
    cudaGetSymbolAddress((void**)&tmp3, g_tmp3);
    cudaGetSymbolAddress((void**)&tmp4, g_tmp4);
    cudaGetSymbolAddress((void**)&pm,   g_pm);
    cudaGetSymbolAddress((void**)&ps,   g_ps);
    cudaGetSymbolAddress((void**)&ff,   g_ff);
    cudaGetSymbolAddress((void**)&h,    g_h);
    cudaGetSymbolAddress((void**)&hc,   g_hc);
    cudaGetSymbolAddress((void**)&h1,   g_h1);
    cudaGetSymbolAddress((void**)&h1c,  g_h1c);
    cudaGetSymbolAddress((void**)&wqc,  g_wqc);
    cudaGetSymbolAddress((void**)&wkc,  g_wkc);
    cudaGetSymbolAddress((void**)&wvc,  g_wvc);
    cudaGetSymbolAddress((void**)&wrc,  g_wrc);
    cudaGetSymbolAddress((void**)&woc,  g_woc);
    cudaGetSymbolAddress((void**)&w1c,  g_w1c);
    cudaGetSymbolAddress((void**)&w2c,  g_w2c);
    cudaGetSymbolAddress((void**)&memc, g_memc);
    cudaGetSymbolAddress((void**)&xc,   g_xc);

    cudaFuncSetAttribute(fused_attn_split, cudaFuncAttributeMaxDynamicSharedMemorySize,
                         SMEM_ATTN_BYTES);

    // single flattened convert launch (exact per-region block counts)
    {
        const int nw = (LL * DDd * DDd) / 1024;        // 4096 blocks each
        const int nf = (LL * DDd * FFf) / 1024;        // 16384
        const int nm = (LL * BB * MMm * DDd) / 1024;   // 4096
        const int nx = (BB * SSq * DDd) / 1024;        // 1024
        CvtP p;
        const float* ins[9]  = {Wq, Wk, Wv, Wr, Wo, W1, W2, memory, x};
        float*       outs[9] = {wqc, wkc, wvc, wrc, woc, w1c, w2c, memc, xc};
        int          cnts[9] = {nw, nw, nw, nw, nw, nf, nf, nm, nx};
        int acc = 0;
        for (int j = 0; j < 9; j++) {
            p.in[j] = ins[j]; p.out[j] = outs[j];
            p.cum[j] = acc; acc += cnts[j];
        }
        p.cum[9] = acc;
        cvt_all9<<<acc, 256>>>(p);
    }

    pos_kernel<<<(TTt * (DDd / 2) + 255) / 256, 256>>>(pos);

    const float* hcur  = x;
    const float* hcurc = xc;
    for (int l = 0; l < LL; l++) {
        dim3 gG(DDd / 128, 48);
        grouped_qkvr<<<gG, 256>>>(hcurc, memc + (size_t)l * BB * MMm * DDd, pos,
                                  wqc + (size_t)l * DDd * DDd, wkc + (size_t)l * DDd * DDd,
                                  wvc + (size_t)l * DDd * DDd, wrc + (size_t)l * DDd * DDd,
                                  q, k, v, r);

        // split-T flash attention: NZ=4 partitions, 2048 CTAs
        dim3 gA(SSq / SMT, BB * HHh, NZ);
        fused_attn_split<<<gA, 256, SMEM_ATTN_BYTES>>>(
            q, k, v, r, rwb + (size_t)l * HHh * DKk, rrb + (size_t)l * HHh * DKk,
            tmp, tmp2, tmp3, tmp4, pm, ps);
        attn_combine<<<(BB * SSq * DDd / 4 + 255) / 256, 256>>>(
            tmp, tmp2, tmp3, tmp4, pm, ps, attn);

        dim3 gO(DDd / 128, (BB * SSq) / 64, 2);
        tc_gemm_splitk<64, 4><<<gO, 256>>>(attn, woc + (size_t)l * DDd * DDd,
                                           tmp, tmp2, DDd, DDd, nullptr);
        ln_kernel2<<<BB * SSq, 256>>>(tmp, tmp2, hcur,
                                      ln1g + l * DDd, ln1b + l * DDd, h1, h1c);

        dim3 gF1(FFf / 128, (BB * SSq) / 128);
        tc_gemm_k<128, 4><<<gF1, 256>>>(h1c, w1c + (size_t)l * DDd * FFf, ff,
                                        FFf, DDd, 1.f, b1 + l * FFf, 1, 1);
        dim3 gF2(DDd / 128, (BB * SSq) / 64, 2);
        tc_gemm_splitk<64, 4><<<gF2, 256>>>(ff, w2c + (size_t)l * FFf * DDd,
                                            tmp, tmp2, DDd, FFf, b2 + l * DDd);

        if (l == LL - 1) {
            ln_kernel2<<<BB * SSq, 256>>>(tmp, tmp2, h1,
                                          ln2g + l * DDd, ln2b + l * DDd, out, nullptr);
        } else {
            ln_kernel2<<<BB * SSq, 256>>>(tmp, tmp2, h1,
                                          ln2g + l * DDd, ln2b + l * DDd, h, hc);
            hcur = h;
            hcurc = hc;
        }
    }
}

// round 14
// speedup vs baseline: 1.0475x; 1.0064x over previous
#include <cuda_runtime.h>
#include <math.h>
#include <stdint.h>

// Problem dims
#define LL  4
#define BB  2
#define SSq 512
#define MMm 512
#define DDd 1024
#define HHh 16
#define DKk 64
#define FFf 4096
#define TTt (SSq + MMm)   // 1024
#define NZ  4             // attention T-split factor

// ---------------- scratch ----------------
__device__ float g_pos[TTt * DDd];        // tf32 bits
__device__ float g_q  [BB * SSq * DDd];   // fp32
__device__ float g_k  [BB * TTt * DDd];   // tf32 bits
__device__ float g_v  [BB * TTt * DDd];   // tf32 bits [b][t][h*64+dk]
__device__ float g_vt [BB * HHh * DKk * TTt]; // tf32 bits [b][h][dk][t]
__device__ float g_r  [TTt * DDd];        // tf32 bits
__device__ float g_attn[BB * SSq * DDd];  // tf32 bits
__device__ float g_tmp [BB * SSq * DDd];
__device__ float g_tmp2[BB * SSq * DDd];
__device__ float g_tmp3[BB * SSq * DDd];
__device__ float g_tmp4[BB * SSq * DDd];
__device__ float g_pm [NZ * BB * HHh * SSq];
__device__ float g_ps [NZ * BB * HHh * SSq];
__device__ float g_ff  [BB * SSq * FFf];  // tf32 bits
__device__ float g_h   [BB * SSq * DDd];  // fp32 residual
__device__ float g_hc  [BB * SSq * DDd];  // tf32 copy
__device__ float g_h1  [BB * SSq * DDd];  // fp32 residual
__device__ float g_h1c [BB * SSq * DDd];  // tf32 copy
// pre-converted operands (tf32 bits)
__device__ float g_wqc[LL * DDd * DDd];
__device__ float g_wkc[LL * DDd * DDd];
__device__ float g_wvc[LL * DDd * DDd];
__device__ float g_wrc[LL * DDd * DDd];
__device__ float g_woc[LL * DDd * DDd];
__device__ float g_w1c[LL * DDd * FFf];
__device__ float g_w2c[LL * FFf * DDd];
__device__ float g_memc[LL * BB * MMm * DDd];
__device__ float g_xc  [BB * SSq * DDd];

// ---------------- PTX helpers ----------------
__device__ __forceinline__ uint32_t f2tf32(float f) {
    uint32_t u;
    asm("cvt.rna.tf32.f32 %0, %1;" : "=r"(u) : "f"(f));
    return u;
}
__device__ __forceinline__ void mma_tf32(float c[4], const uint32_t a[4], const uint32_t b[2]) {
    asm volatile(
        "mma.sync.aligned.m16n8k8.row.col.f32.tf32.tf32.f32 "
        "{%0,%1,%2,%3},{%4,%5,%6,%7},{%8,%9},{%0,%1,%2,%3};"
        : "+f"(c[0]), "+f"(c[1]), "+f"(c[2]), "+f"(c[3])
        : "r"(a[0]), "r"(a[1]), "r"(a[2]), "r"(a[3]), "r"(b[0]), "r"(b[1]));
}
__device__ __forceinline__ void cp_async16(void* smem, const void* g) {
    uint32_t s = (uint32_t)__cvta_generic_to_shared(smem);
    asm volatile("cp.async.cg.shared.global [%0], [%1], 16;" :: "r"(s), "l"(g));
}
#define CP_COMMIT() asm volatile("cp.async.commit_group;")
#define CP_WAIT(n)  asm volatile("cp.async.wait_group %0;" :: "n"(n))

__device__ __forceinline__ uint32_t sm_u32(const void* p) {
    return (uint32_t)__cvta_generic_to_shared(p);
}
__device__ __forceinline__ void ldsm_x4(uint32_t r[4], uint32_t addr) {
    asm volatile("ldmatrix.sync.aligned.m8n8.x4.shared.b16 {%0,%1,%2,%3}, [%4];"
                 : "=r"(r[0]), "=r"(r[1]), "=r"(r[2]), "=r"(r[3]) : "r"(addr));
}
__device__ __forceinline__ void ldsm_x2(uint32_t r[2], uint32_t addr) {
    asm volatile("ldmatrix.sync.aligned.m8n8.x2.shared.b16 {%0,%1}, [%2];"
                 : "=r"(r[0]), "=r"(r[1]) : "r"(addr));
}

// ---------------- flattened 9-region fp32 -> tf32-bit convert ----------------
struct CvtP {
    const float* in[9];
    float* out[9];
    int cum[10];
};
__global__ void cvt_all9(CvtP p)
{
    int blk = blockIdx.x;
    int r = 0;
#pragma unroll
    for (int j = 1; j < 9; j++) r += (blk >= p.cum[j]);
    int i = (blk - p.cum[r]) * 256 + threadIdx.x;
    float4 v = ((const float4*)p.in[r])[i];
    uint4 u = make_uint4(f2tf32(v.x), f2tf32(v.y), f2tf32(v.z), f2tf32(v.w));
    ((uint4*)p.out[r])[i] = u;
}

// ---------------- positional encodings (tf32 out) ----------------
__global__ void pos_kernel(float* __restrict__ pos)
{
    int idx = blockIdx.x * blockDim.x + threadIdx.x;
    if (idx >= TTt * (DDd / 2)) return;
    int t = idx / (DDd / 2), j = idx % (DDd / 2);
    double invf = exp(((double)(-2 * j) / (double)DDd) * 9.210340371976184);
    double ang  = (double)(TTt - 1 - t) * invf;
    double kk   = floor(ang * 0.15915494309189535);
    float a = (float)(ang - kk * 6.283185307179586);
    pos[(size_t)t * DDd + j]           = __uint_as_float(f2tf32(sinf(a)));
    pos[(size_t)t * DDd + j + DDd / 2] = __uint_as_float(f2tf32(cosf(a)));
}

// ---------------- V transpose: [b][t][h*64+dk] -> [b][h][dk][t] ----------------
__global__ void vtrans_kernel(const float* __restrict__ v, float* __restrict__ vt)
{
    __shared__ float tile[32][33];
    int bh = blockIdx.z;               // b*HHh + h
    int b = bh >> 4, h = bh & 15;
    int t0 = blockIdx.x * 32;
    int d0 = blockIdx.y * 32;
    int tx = threadIdx.x, ty = threadIdx.y;   // 32 x 8
#pragma unroll
    for (int j = 0; j < 4; j++) {
        int t = t0 + ty + j * 8;
        tile[ty + j * 8][tx] = v[((size_t)b * TTt + t) * DDd + h * DKk + d0 + tx];
    }
    __syncthreads();
#pragma unroll
    for (int j = 0; j < 4; j++) {
        int d = d0 + ty + j * 8;
        vt[((size_t)bh * DKk + d) * TTt + t0 + tx] = tile[tx][ty + j * 8];
    }
}

// ======================================================================
// Async GEMM core (R9 verified): pre-converted tf32 operands.
// ======================================================================
template<int BM, int NWN>
__device__ __forceinline__ void gemm_core_async(
    const float* __restrict__ Ag, const float* __restrict__ Bg, float* __restrict__ Cg,
    int N, int K, int lda, float alpha, const float* __restrict__ biasg, int relu,
    int cvt_out)
{
    constexpr int BN = NWN * 32;
    constexpr int NWM = 8 / NWN;
    constexpr int WM = BM / NWM;
    constexpr int MT = WM / 16;
    constexpr int BPITCH = BN + 8;
    constexpr int NA_CH = BM / 64;
    constexpr int NB_CH = BN / 64;

    __shared__ uint32_t As[2][BM][20];
    __shared__ uint32_t Bs[2][16][BPITCH];

    int tid = threadIdx.x, lane = tid & 31, warp = tid >> 5;
    int g = lane >> 2, tg = lane & 3;
    int warp_m = warp % NWM, warp_n = warp / NWM;
    int wm = warp_m * WM, wn = warp_n * 32;

    float acc[MT][4][4];
#pragma unroll
    for (int mt = 0; mt < MT; mt++)
#pragma unroll
        for (int nt = 0; nt < 4; nt++)
#pragma unroll
            for (int i = 0; i < 4; i++) acc[mt][nt][i] = 0.f;

    int ar[NA_CH], ak[NA_CH];
#pragma unroll
    for (int j = 0; j < NA_CH; j++) {
        int c = tid + j * 256;
        ar[j] = c >> 2; ak[j] = (c & 3) * 4;
    }
    int bk[NB_CH], bn[NB_CH];
#pragma unroll
    for (int j = 0; j < NB_CH; j++) {
        int c = tid + j * 256;
        if (BN == 128) { bk[j] = c >> 5; bn[j] = (c & 31) * 4; }
        else           { bk[j] = c >> 4; bn[j] = (c & 15) * 4; }
    }

    int nk = K / 16;

#pragma unroll
    for (int j = 0; j < NA_CH; j++)
        cp_async16(&As[0][ar[j]][ak[j]], Ag + (size_t)ar[j] * lda + ak[j]);
#pragma unroll
    for (int j = 0; j < NB_CH; j++)
        cp_async16(&Bs[0][bk[j]][bn[j]], Bg + (size_t)bk[j] * N + bn[j]);
    CP_COMMIT();

    for (int kt = 0; kt < nk; kt++) {
        int buf = kt & 1;
        bool more = (kt + 1 < nk);
        if (more) {
            int nb = buf ^ 1;
#pragma unroll
            for (int j = 0; j < NA_CH; j++)
                cp_async16(&As[nb][ar[j]][ak[j]],
                           Ag + (size_t)ar[j] * lda + (kt + 1) * 16 + ak[j]);
#pragma unroll
            for (int j = 0; j < NB_CH; j++)
                cp_async16(&Bs[nb][bk[j]][bn[j]],
                           Bg + (size_t)((kt + 1) * 16 + bk[j]) * N + bn[j]);
            CP_COMMIT();
            CP_WAIT(1);
        } else {
            CP_WAIT(0);
        }
        __syncthreads();

#pragma unroll
        for (int ks = 0; ks < 2; ks++) {
            uint32_t af[MT][4], bf[4][2];
#pragma unroll
            for (int mt = 0; mt < MT; mt++) {
                int row = wm + mt * 16;
                af[mt][0] = As[buf][row + g][ks * 8 + tg];
                af[mt][1] = As[buf][row + g + 8][ks * 8 + tg];
                af[mt][2] = As[buf][row + g][ks * 8 + tg + 4];
                af[mt][3] = As[buf][row + g + 8][ks * 8 + tg + 4];
            }
#pragma unroll
            for (int nt = 0; nt < 4; nt++) {
                int col = wn + nt * 8 + g;
                bf[nt][0] = Bs[buf][ks * 8 + tg][col];
                bf[nt][1] = Bs[buf][ks * 8 + tg + 4][col];
            }
#pragma unroll
            for (int mt = 0; mt < MT; mt++)
#pragma unroll
                for (int nt = 0; nt < 4; nt++) mma_tf32(acc[mt][nt], af[mt], bf[nt]);
        }
        if (more) __syncthreads();
    }

#pragma unroll
    for (int mt = 0; mt < MT; mt++) {
#pragma unroll
        for (int nt = 0; nt < 4; nt++) {
            int row = wm + mt * 16 + g;
            int col = wn + nt * 8 + tg * 2;
            float bx0 = 0.f, bx1 = 0.f;
            if (biasg) { bx0 = biasg[col]; bx1 = biasg[col + 1]; }
            float v0 = acc[mt][nt][0] * alpha + bx0;
            float v1 = acc[mt][nt][1] * alpha + bx1;
            float v2 = acc[mt][nt][2] * alpha + bx0;
            float v3 = acc[mt][nt][3] * alpha + bx1;
            if (relu) {
                v0 = fmaxf(v0, 0.f); v1 = fmaxf(v1, 0.f);
                v2 = fmaxf(v2, 0.f); v3 = fmaxf(v3, 0.f);
            }
            if (cvt_out) {
                v0 = __uint_as_float(f2tf32(v0));
                v1 = __uint_as_float(f2tf32(v1));
                v2 = __uint_as_float(f2tf32(v2));
                v3 = __uint_as_float(f2tf32(v3));
            }
            *(float2*)(Cg + (size_t)row * N + col)       = make_float2(v0, v1);
            *(float2*)(Cg + (size_t)(row + 8) * N + col) = make_float2(v2, v3);
        }
    }
}

template<int BM, int NWN>
__global__ void __launch_bounds__(256) tc_gemm_k(
    const float* __restrict__ A, const float* __restrict__ B, float* __restrict__ C,
    int N, int K, float alpha, const float* __restrict__ bias, int relu, int cvt_out)
{
    constexpr int BN = NWN * 32;
    const float* Ag = A + (size_t)blockIdx.y * BM * K;
    const float* Bg = B + (size_t)blockIdx.x * BN;
    float* Cg = C + (size_t)blockIdx.y * BM * N + (size_t)blockIdx.x * BN;
    const float* bg = bias ? bias + (size_t)blockIdx.x * BN : nullptr;
    gemm_core_async<BM, NWN>(Ag, Bg, Cg, N, K, K, alpha, bg, relu, cvt_out);
}

template<int BM, int NWN>
__global__ void __launch_bounds__(256) tc_gemm_splitk(
    const float* __restrict__ A, const float* __restrict__ B,
    float* __restrict__ C0, float* __restrict__ C1,
    int N, int K, const float* __restrict__ bias)
{
    constexpr int BN = NWN * 32;
    int z = blockIdx.z;
    int K2 = K >> 1;
    const float* Ag = A + (size_t)blockIdx.y * BM * K + (size_t)z * K2;
    const float* Bg = B + (size_t)z * K2 * N + (size_t)blockIdx.x * BN;
    float* C = z ? C1 : C0;
    float* Cg = C + (size_t)blockIdx.y * BM * N + (size_t)blockIdx.x * BN;
    const float* bg = (bias && z == 0) ? bias + (size_t)blockIdx.x * BN : nullptr;
    gemm_core_async<BM, NWN>(Ag, Bg, Cg, N, K2, K, 1.f, bg, 0, 0);
}

// grouped q/k/v/r projections (R9 verified)
__global__ void __launch_bounds__(256) grouped_qkvr(
    const float* __restrict__ hcc, const float* __restrict__ memc, const float* __restrict__ pos,
    const float* __restrict__ Wq, const float* __restrict__ Wk,
    const float* __restrict__ Wv, const float* __restrict__ Wr,
    float* __restrict__ q, float* __restrict__ k, float* __restrict__ v, float* __restrict__ r)
{
    int y = blockIdx.y;
    const float* Ag; const float* B; float* C; float alpha = 1.f; int cvt = 1;
    if (y < 8) {
        Ag = hcc + (size_t)y * 128 * DDd; B = Wq; C = q + (size_t)y * 128 * DDd;
        alpha = 0.125f; cvt = 0;
    } else if (y < 40) {
        int yy = (y < 24) ? y - 8 : y - 24;
        int row0 = yy * 128;
        int b = row0 >> 10, t0 = row0 & 1023;
        Ag = (t0 < MMm) ? memc + ((size_t)b * MMm + t0) * DDd
                        : hcc  + ((size_t)b * SSq + (t0 - MMm)) * DDd;
        if (y < 24) { B = Wk; C = k + (size_t)yy * 128 * DDd; }
        else        { B = Wv; C = v + (size_t)yy * 128 * DDd; }
    } else {
        int yy = y - 40;
        Ag = pos + (size_t)yy * 128 * DDd; B = Wr; C = r + (size_t)yy * 128 * DDd;
    }
    const float* Bg = B + (size_t)blockIdx.x * 128;
    float* Cg = C + (size_t)blockIdx.x * 128;
    gemm_core_async<128, 4>(Ag, Bg, Cg, DDd, DDd, DDd, alpha, nullptr, 0, cvt);
}

// ======================================================================
// Flash fused attention, split over T into NZ partitions. V consumed
// TRANSPOSED ([dk][t]) so P@V uses ldmatrix for both operands.
// ======================================================================
#define SMT   32
#define TN    64
#define QPITCH 68
#define WPITCH 100
#define SMEM_ATTN_FLOATS (2*SMT*QPITCH + 64*QPITCH + 96*QPITCH + 64*QPITCH + SMT*QPITCH + SMT*WPITCH + 96)
#define SMEM_ATTN_BYTES  (SMEM_ATTN_FLOATS * 4)

__global__ void __launch_bounds__(256) fused_attn_split(
    const float* __restrict__ q, const float* __restrict__ k, const float* __restrict__ vt,
    const float* __restrict__ r, const float* __restrict__ rwb, const float* __restrict__ rrb,
    float* __restrict__ o0, float* __restrict__ o1,
    float* __restrict__ o2, float* __restrict__ o3,
    float* __restrict__ pm, float* __restrict__ ps)
{
    extern __shared__ float sm[];
    uint32_t* Qcb  = (uint32_t*)sm;
    uint32_t* Qrb  = Qcb + SMT * QPITCH;
    uint32_t* Ktb  = Qrb + SMT * QPITCH;
    uint32_t* Rwb  = Ktb + 64 * QPITCH;
    uint32_t* Vtb  = Rwb + 96 * QPITCH;   // [64 dk][68 t]
    float*    Lt   = (float*)(Vtb + 64 * QPITCH);
    float*    QRW  = Lt + SMT * QPITCH;
    float*    crow = QRW + SMT * WPITCH;
    float*    rowm = crow + 32;
    float*    rowsum = rowm + 32;
    uint32_t* Ltb  = (uint32_t*)Lt;

    int tid = threadIdx.x, lane = tid & 31, warp = tid >> 5;
    int g = lane >> 2, tg = lane & 3;
    int s0 = (15 - blockIdx.x) * SMT;
    int b = blockIdx.y >> 4, h = blockIdx.y & 15;
    int z = blockIdx.z;

    const float* qb = q + (size_t)b * SSq * DDd + h * DKk;
    const float* kb = k + (size_t)b * TTt * DDd + h * DKk;
    const float* vtb = vt + (size_t)(b * HHh + h) * DKk * TTt;   // [dk][t]
    const float* rb = r + h * DKk;
    const float* wbv = rwb + h * DKk;
    const float* rbv = rrb + h * DKk;

    int ntiles = (s0 + 543) / 64 + 1;
    int tbeg = (z * ntiles) / NZ;
    int tend = ((z + 1) * ntiles) / NZ;

    int lrow = tid >> 4, lk0 = (tid & 15) * 4;

    auto issue_KR = [&](int it) {
        if (it < tend) {
            int t0 = it * TN, jb = t0 - s0 + 480;
#pragma unroll
            for (int j = 0; j < 4; j++) {
                int row = lrow + j * 16;
                cp_async16(&Ktb[row * QPITCH + lk0], kb + (size_t)(t0 + row) * DDd + lk0);
            }
#pragma unroll
            for (int j = 0; j < 6; j++) {
                int row = lrow + j * 16;
                int jg = jb + row;
                if (jg > TTt - 1) jg = TTt - 1;
                if (jg < 0) jg = 0;
                cp_async16(&Rwb[row * QPITCH + lk0], rb + (size_t)jg * DDd + lk0);
            }
        }
        CP_COMMIT();
    };
    auto issue_V = [&](int it) {
        if (it < tend) {
            int t0 = it * TN;
#pragma unroll
            for (int j = 0; j < 4; j++) {
                int row = lrow + j * 16;   // dk row
                cp_async16(&Vtb[row * QPITCH + lk0], vtb + (size_t)row * TTt + t0 + lk0);
            }
        }
        CP_COMMIT();
    };

    issue_KR(tbeg);

#pragma unroll
    for (int j = 0; j < 2; j++) {
        int c = tid + j * 256;
        int row = c >> 4, k0 = (c & 15) * 4;
        float4 qv = *(const float4*)(qb + (size_t)(s0 + row) * DDd + k0);
        float4 w4 = *(const float4*)(wbv + k0);
        float4 r4 = *(const float4*)(rbv + k0);
        Qcb[row * QPITCH + k0 + 0] = f2tf32(qv.x + w4.x);
        Qcb[row * QPITCH + k0 + 1] = f2tf32(qv.y + w4.y);
        Qcb[row * QPITCH + k0 + 2] = f2tf32(qv.z + w4.z);
        Qcb[row * QPITCH + k0 + 3] = f2tf32(qv.w + w4.w);
        Qrb[row * QPITCH + k0 + 0] = f2tf32(qv.x + r4.x);
        Qrb[row * QPITCH + k0 + 1] = f2tf32(qv.y + r4.y);
        Qrb[row * QPITCH + k0 + 2] = f2tf32(qv.z + r4.z);
        Qrb[row * QPITCH + k0 + 3] = f2tf32(qv.w + r4.w);
    }
    if (tid < 32) { rowm[tid] = -1e30f; rowsum[tid] = 0.f; }

    int wm2 = (warp & 1) * 16;
    int wn2 = (warp >> 1) * 16;
    int wn3 = (warp >> 1) * 24;
    int r1 = wm2 + g, r2 = r1 + 8;

    int srow = warp * 4 + (lane >> 3);
    int scol = (lane & 7) * 8;

    int a_row = (lane & 7) + ((lane >> 3) & 1) * 8;
    int a_col = (lane >> 4) * 4;
    int b_row = (lane & 7) + ((lane >> 4) & 1) * 8;
    int b_col = ((lane >> 3) & 1) * 4;
    int c_row = lane & 7;
    int c_col = ((lane >> 3) & 1) * 4;

    uint32_t qc_a  = sm_u32(&Qcb[(wm2 + a_row) * QPITCH + a_col]);
    uint32_t qr_a  = sm_u32(&Qrb[(wm2 + a_row) * QPITCH + a_col]);
    uint32_t lt_a  = sm_u32(&Ltb[(wm2 + a_row) * QPITCH + a_col]);
    uint32_t kt_a  = sm_u32(&Ktb[(wn2 + b_row) * QPITCH + b_col]);
    uint32_t vt_a  = sm_u32(&Vtb[(wn2 + b_row) * QPITCH + b_col]);
    uint32_t rw4_a = sm_u32(&Rwb[(wn3 + b_row) * QPITCH + b_col]);
    uint32_t rw2_a = sm_u32(&Rwb[(wn3 + 16 + c_row) * QPITCH + c_col]);

    float oacc[2][4];
#pragma unroll
    for (int nt = 0; nt < 2; nt++)
#pragma unroll
        for (int i = 0; i < 4; i++) oacc[nt][i] = 0.f;

    for (int it = tbeg; it < tend; it++) {
        int t0 = it * TN;
        CP_WAIT(0);
        __syncthreads();     // sync A

        issue_V(it);

        float ca[2][4], ra[3][4];
#pragma unroll
        for (int nt = 0; nt < 2; nt++)
#pragma unroll
            for (int i = 0; i < 4; i++) ca[nt][i] = 0.f;
#pragma unroll
        for (int nt = 0; nt < 3; nt++)
#pragma unroll
            for (int i = 0; i < 4; i++) ra[nt][i] = 0.f;

#pragma unroll
        for (int k8 = 0; k8 < 64; k8 += 8) {
            uint32_t koff = k8 * 4;
            uint32_t af[4], afr[4], bk4[4], br4[4], br2[2];
            ldsm_x4(af,  qc_a + koff);
            ldsm_x4(afr, qr_a + koff);
            ldsm_x4(bk4, kt_a + koff);
            ldsm_x4(br4, rw4_a + koff);
            ldsm_x2(br2, rw2_a + koff);
            {
                uint32_t bf0[2] = {bk4[0], bk4[1]};
                uint32_t bf1[2] = {bk4[2], bk4[3]};
                mma_tf32(ca[0], af, bf0);
                mma_tf32(ca[1], af, bf1);
            }
            {
                uint32_t bf0[2] = {br4[0], br4[1]};
                uint32_t bf1[2] = {br4[2], br4[3]};
                mma_tf32(ra[0], afr, bf0);
                mma_tf32(ra[1], afr, bf1);
                mma_tf32(ra[2], afr, br2);
            }
        }
#pragma unroll
        for (int nt = 0; nt < 2; nt++) {
            int c0 = wn2 + nt * 8 + tg * 2;
            Lt[r1 * QPITCH + c0]     = ca[nt][0];
            Lt[r1 * QPITCH + c0 + 1] = ca[nt][1];
            Lt[r2 * QPITCH + c0]     = ca[nt][2];
            Lt[r2 * QPITCH + c0 + 1] = ca[nt][3];
        }
#pragma unroll
        for (int nt = 0; nt < 3; nt++) {
            int c0 = wn3 + nt * 8 + tg * 2;
            QRW[r1 * WPITCH + c0]     = ra[nt][0];
            QRW[r1 * WPITCH + c0 + 1] = ra[nt][1];
            QRW[r2 * WPITCH + c0]     = ra[nt][2];
            QRW[r2 * WPITCH + c0 + 1] = ra[nt][3];
        }
        __syncthreads();     // sync B

        issue_KR(it + 1);

        // warp-exclusive row softmax
        {
            float4 ca4 = *(const float4*)&Lt[srow * QPITCH + scol];
            float4 cb4 = *(const float4*)&Lt[srow * QPITCH + scol + 4];
            float lv[8] = {ca4.x, ca4.y, ca4.z, ca4.w, cb4.x, cb4.y, cb4.z, cb4.w};
            const float* qr = &QRW[srow * WPITCH + scol + 31 - srow];
            int lim = MMm - t0 + s0 + srow;
#pragma unroll
            for (int j = 0; j < 8; j++) {
                float lvv = lv[j] + qr[j];
                lv[j] = (scol + j <= lim) ? lvv : -1e30f;
            }
            float tmax = lv[0];
#pragma unroll
            for (int j = 1; j < 8; j++) tmax = fmaxf(tmax, lv[j]);
            tmax = fmaxf(tmax, __shfl_xor_sync(0xffffffffu, tmax, 1));
            tmax = fmaxf(tmax, __shfl_xor_sync(0xffffffffu, tmax, 2));
            tmax = fmaxf(tmax, __shfl_xor_sync(0xffffffffu, tmax, 4));
            float m_old = rowm[srow];
            float m_new = fmaxf(m_old, tmax);
            float cfac = __expf(m_old - m_new);
            float p[8], tsum = 0.f;
#pragma unroll
            for (int j = 0; j < 8; j++) {
                p[j] = __expf(lv[j] - m_new);
                tsum += p[j];
            }
            tsum += __shfl_xor_sync(0xffffffffu, tsum, 1);
            tsum += __shfl_xor_sync(0xffffffffu, tsum, 2);
            tsum += __shfl_xor_sync(0xffffffffu, tsum, 4);
            uint4 u0 = make_uint4(f2tf32(p[0]), f2tf32(p[1]), f2tf32(p[2]), f2tf32(p[3]));
            uint4 u1 = make_uint4(f2tf32(p[4]), f2tf32(p[5]), f2tf32(p[6]), f2tf32(p[7]));
            *(uint4*)&Ltb[srow * QPITCH + scol]     = u0;
            *(uint4*)&Ltb[srow * QPITCH + scol + 4] = u1;
            if ((lane & 7) == 0) {
                rowm[srow] = m_new;
                rowsum[srow] = rowsum[srow] * cfac + tsum;
                crow[srow] = cfac;
            }
        }

        CP_WAIT(1);
        __syncthreads();     // sync C

        float c1 = crow[r1], c2 = crow[r2];
#pragma unroll
        for (int nt = 0; nt < 2; nt++) {
            oacc[nt][0] *= c1; oacc[nt][1] *= c1;
            oacc[nt][2] *= c2; oacc[nt][3] *= c2;
        }
#pragma unroll
        for (int k8 = 0; k8 < 64; k8 += 8) {
            uint32_t af[4], bv4[4];
            ldsm_x4(af, lt_a + k8 * 4);
            ldsm_x4(bv4, vt_a + k8 * 4);
            {
                uint32_t bf0[2] = {bv4[0], bv4[1]};
                uint32_t bf1[2] = {bv4[2], bv4[3]};
                mma_tf32(oacc[0], af, bf0);
                mma_tf32(oacc[1], af, bf1);
            }
        }
    }

    __syncthreads();
    float* ozb = (z == 0) ? o0 : (z == 1) ? o1 : (z == 2) ? o2 : o3;
    float* oz = ozb + ((size_t)b * SSq + s0) * DDd + h * DKk;
#pragma unroll
    for (int nt = 0; nt < 2; nt++) {
        int c0 = wn2 + nt * 8 + tg * 2;
        *(float2*)(oz + (size_t)r1 * DDd + c0) = make_float2(oacc[nt][0], oacc[nt][1]);
        *(float2*)(oz + (size_t)r2 * DDd + c0) = make_float2(oacc[nt][2], oacc[nt][3]);
    }
    if (warp < 2 && tg == 0) {
        int zoff = z * (BB * HHh * SSq);
        int base = blockIdx.y * SSq + s0;
        pm[zoff + base + r1] = rowm[r1];
        ps[zoff + base + r1] = rowsum[r1];
        pm[zoff + base + r2] = rowm[r2];
        ps[zoff + base + r2] = rowsum[r2];
    }
}

// ---------------- combine NZ split-attention partials -> attn (tf32 bits) ---
__global__ void attn_combine(const float* __restrict__ o0, const float* __restrict__ o1,
                             const float* __restrict__ o2, const float* __restrict__ o3,
                             const float* __restrict__ pm, const float* __restrict__ ps,
                             float* __restrict__ attn)
{
    int i = blockIdx.x * 256 + threadIdx.x;     // float4 index
    if (i >= (BB * SSq * DDd) / 4) return;
    int e = i * 4;
    int d = e & (DDd - 1);
    int h = d >> 6;
    int s = (e >> 10) & (SSq - 1);
    int b = e >> 19;
    int row = (b * HHh + h) * SSq + s;
    const int Z = BB * HHh * SSq;
    float m0 = pm[row], m1 = pm[Z + row], m2 = pm[2 * Z + row], m3 = pm[3 * Z + row];
    float s0v = ps[row], s1v = ps[Z + row], s2v = ps[2 * Z + row], s3v = ps[3 * Z + row];
    float m = fmaxf(fmaxf(m0, m1), fmaxf(m2, m3));
    float c0 = __expf(m0 - m), c1 = __expf(m1 - m);
    float c2 = __expf(m2 - m), c3 = __expf(m3 - m);
    float inv = 1.f / (c0 * s0v + c1 * s1v + c2 * s2v + c3 * s3v);
    float4 a0 = ((const float4*)o0)[i];
    float4 a1 = ((const float4*)o1)[i];
    float4 a2 = ((const float4*)o2)[i];
    float4 a3 = ((const float4*)o3)[i];
    uint4 u;
    u.x = f2tf32((c0 * a0.x + c1 * a1.x + c2 * a2.x + c3 * a3.x) * inv);
    u.y = f2tf32((c0 * a0.y + c1 * a1.y + c2 * a2.y + c3 * a3.y) * inv);
    u.z = f2tf32((c0 * a0.z + c1 * a1.z + c2 * a2.z + c3 * a3.z) * inv);
    u.w = f2tf32((c0 * a0.w + c1 * a1.w + c2 * a2.w + c3 * a3.w) * inv);
    ((uint4*)attn)[i] = u;
}

// ---------------- residual + LayerNorm over (x0 + x1 + res), dual output ----------------
__global__ void ln_kernel2(const float* __restrict__ x0, const float* __restrict__ x1,
                           const float* __restrict__ res,
                           const float* __restrict__ g, const float* __restrict__ b,
                           float* __restrict__ out, float* __restrict__ outc)
{
    int row = blockIdx.x;
    const float* xr0 = x0 + (size_t)row * DDd;
    const float* xr1 = x1 + (size_t)row * DDd;
    const float* rr  = res + (size_t)row * DDd;
    __shared__ float redA[33], redB[33];
    int tid = threadIdx.x;

    float loc[4];
    float s1 = 0.f, s2 = 0.f;
#pragma unroll
    for (int i = 0; i < 4; i++) {
        int d = tid + i * 256;
        float v = xr0[d] + xr1[d] + rr[d];
        loc[i] = v;
        s1 += v;
        s2 += v * v;
    }
#pragma unroll
    for (int o = 16; o; o >>= 1) {
        s1 += __shfl_xor_sync(0xffffffffu, s1, o);
        s2 += __shfl_xor_sync(0xffffffffu, s2, o);
    }
    if ((tid & 31) == 0) { redA[tid >> 5] = s1; redB[tid >> 5] = s2; }
    __syncthreads();
    if (tid < 32) {
        float a = (tid < 8) ? redA[tid] : 0.f;
        float c = (tid < 8) ? redB[tid] : 0.f;
#pragma unroll
        for (int o = 4; o; o >>= 1) {
            a += __shfl_xor_sync(0xffffffffu, a, o);
            c += __shfl_xor_sync(0xffffffffu, c, o);
        }
        if (tid == 0) { redA[32] = a; redB[32] = c; }
    }
    __syncthreads();
    float mu  = redA[32] * (1.f / DDd);
    float var = redB[32] * (1.f / DDd) - mu * mu;
    float rstd = rsqrtf(var + 1e-5f);
#pragma unroll
    for (int i = 0; i < 4; i++) {
        int d = tid + i * 256;
        float o = (loc[i] - mu) * rstd * g[d] + b[d];
        out[(size_t)row * DDd + d] = o;
        if (outc) outc[(size_t)row * DDd + d] = __uint_as_float(f2tf32(o));
    }
}

// ---------------- host-side orchestration ----------------
extern "C" void kernel_launch(void* const* d_in, const int* in_sizes, int n_in,
                              void* d_out, int out_size)
{
    const float* x      = (const float*)d_in[0];
    const float* memory = (const float*)d_in[1];
    const float* Wq  = (const float*)d_in[2];
    const float* Wk  = (const float*)d_in[3];
    const float* Wv  = (const float*)d_in[4];
    const float* Wr  = (const float*)d_in[5];
    const float* Wo  = (const float*)d_in[6];
    const float* rwb = (const float*)d_in[7];
    const float* rrb = (const float*)d_in[8];
    const float* ln1g = (const float*)d_in[9];
    const float* ln1b = (const float*)d_in[10];
    const float* ln2g = (const float*)d_in[11];
    const float* ln2b = (const float*)d_in[12];
    const float* W1  = (const float*)d_in[13];
    const float* b1  = (const float*)d_in[14];
    const float* W2  = (const float*)d_in[15];
    const float* b2  = (const float*)d_in[16];
    float* out = (float*)d_out;

    float *pos, *q, *k, *v, *vt, *r, *attn, *tmp, *tmp2, *tmp3, *tmp4, *pm, *ps;
    float *ff, *h, *hc, *h1, *h1c;
    float *wqc, *wkc, *wvc, *wrc, *woc, *w1c, *w2c, *memc, *xc;
    cudaGetSymbolAddress((void**)&pos,  g_pos);
    cudaGetSymbolAddress((void**)&q,    g_q);
    cudaGetSymbolAddress((void**)&k,    g_k);
    cudaGetSymbolAddress((void**)&v,    g_v);
    cudaGetSymbolAddress((void**)&vt,   g_vt);
    cudaGetSymbolAddress((void**)&r,    g_r);
    cudaGetSymbolAddress((void**)&attn, g_attn);
    cudaGetSymbolAddress((void**)&tmp,  g_tmp);
    cudaGetSymbolAddress((void**)&tmp2, g_tmp2);
    cudaGetSymbolAddress((void**)&tmp3, g_tmp3);
    cudaGetSymbolAddress((void**)&tmp4, g_tmp4);
    cudaGetSymbolAddress((void**)&pm,   g_pm);
    cudaGetSymbolAddress((void**)&ps,   g_ps);
    cudaGetSymbolAddress((void**)&ff,   g_ff);
    cudaGetSymbolAddress((void**)&h,    g_h);
    cudaGetSymbolAddress((void**)&hc,   g_hc);
    cudaGetSymbolAddress((void**)&h1,   g_h1);
    cudaGetSymbolAddress((void**)&h1c,  g_h1c);
    cudaGetSymbolAddress((void**)&wqc,  g_wqc);
    cudaGetSymbolAddress((void**)&wkc,  g_wkc);
    cudaGetSymbolAddress((void**)&wvc,  g_wvc);
    cudaGetSymbolAddress((void**)&wrc,  g_wrc);
    cudaGetSymbolAddress((void**)&woc,  g_woc);
    cudaGetSymbolAddress((void**)&w1c,  g_w1c);
    cudaGetSymbolAddress((void**)&w2c,  g_w2c);
    cudaGetSymbolAddress((void**)&memc, g_memc);
    cudaGetSymbolAddress((void**)&xc,   g_xc);

    cudaFuncSetAttribute(fused_attn_split, cudaFuncAttributeMaxDynamicSharedMemorySize,
                         SMEM_ATTN_BYTES);

    // single flattened convert launch
    {
        const int nw = (LL * DDd * DDd) / 1024;
        const int nf = (LL * DDd * FFf) / 1024;
        const int nm = (LL * BB * MMm * DDd) / 1024;
        const int nx = (BB * SSq * DDd) / 1024;
        CvtP p;
        const float* ins[9]  = {Wq, Wk, Wv, Wr, Wo, W1, W2, memory, x};
        float*       outs[9] = {wqc, wkc, wvc, wrc, woc, w1c, w2c, memc, xc};
        int          cnts[9] = {nw, nw, nw, nw, nw, nf, nf, nm, nx};
        int acc = 0;
        for (int j = 0; j < 9; j++) {
            p.in[j] = ins[j]; p.out[j] = outs[j];
            p.cum[j] = acc; acc += cnts[j];
        }
        p.cum[9] = acc;
        cvt_all9<<<acc, 256>>>(p);
    }

    pos_kernel<<<(TTt * (DDd / 2) + 255) / 256, 256>>>(pos);

    const float* hcur  = x;
    const float* hcurc = xc;
    for (int l = 0; l < LL; l++) {
        dim3 gG(DDd / 128, 48);
        grouped_qkvr<<<gG, 256>>>(hcurc, memc + (size_t)l * BB * MMm * DDd, pos,
                                  wqc + (size_t)l * DDd * DDd, wkc + (size_t)l * DDd * DDd,
                                  wvc + (size_t)l * DDd * DDd, wrc + (size_t)l * DDd * DDd,
                                  q, k, v, r);

        // transpose V -> [b][h][dk][t]
        dim3 gT(TTt / 32, DKk / 32, BB * HHh);
        vtrans_kernel<<<gT, dim3(32, 8)>>>(v, vt);

        // split-T flash attention: NZ=4 partitions, 2048 CTAs
        dim3 gA(SSq / SMT, BB * HHh, NZ);
        fused_attn_split<<<gA, 256, SMEM_ATTN_BYTES>>>(
            q, k, vt, r, rwb + (size_t)l * HHh * DKk, rrb + (size_t)l * HHh * DKk,
            tmp, tmp2, tmp3, tmp4, pm, ps);
        attn_combine<<<(BB * SSq * DDd / 4 + 255) / 256, 256>>>(
            tmp, tmp2, tmp3, tmp4, pm, ps, attn);

        dim3 gO(DDd / 128, (BB * SSq) / 64, 2);
        tc_gemm_splitk<64, 4><<<gO, 256>>>(attn, woc + (size_t)l * DDd * DDd,
                                           tmp, tmp2, DDd, DDd, nullptr);
        ln_kernel2<<<BB * SSq, 256>>>(tmp, tmp2, hcur,
                                      ln1g + l * DDd, ln1b + l * DDd, h1, h1c);

        dim3 gF1(FFf / 128, (BB * SSq) / 128);
        tc_gemm_k<128, 4><<<gF1, 256>>>(h1c, w1c + (size_t)l * DDd * FFf, ff,
                                        FFf, DDd, 1.f, b1 + l * FFf, 1, 1);
        dim3 gF2(DDd / 128, (BB * SSq) / 64, 2);
        tc_gemm_splitk<64, 4><<<gF2, 256>>>(ff, w2c + (size_t)l * FFf * DDd,
                                            tmp, tmp2, DDd, FFf, b2 + l * DDd);

        if (l == LL - 1) {
            ln_kernel2<<<BB * SSq, 256>>>(tmp, tmp2, h1,
                                          ln2g + l * DDd, ln2b + l * DDd, out, nullptr);
        } else {
            ln_kernel2<<<BB * SSq, 256>>>(tmp, tmp2, h1,
                                          ln2g + l * DDd, ln2b + l * DDd, h, hc);
            hcur = h;
            hcurc = hc;
        }
    }
}